// round 8
// baseline (speedup 1.0000x reference)
#include <cuda_runtime.h>
#include <cuda_bf16.h>
#include <cstdint>

#define BATCH 4
#define S_LEN 2048
#define EMB   1024
#define NH    16
#define HD    64
#define MTOT  (BATCH * S_LEN)   // 8192

// ---------------------------------------------------------------------------
// Device-global scratch (allocation-free requirement)
// ---------------------------------------------------------------------------
static __device__ __nv_bfloat16 g_Ah[MTOT * EMB];        // GEMM A hi (x split, then attn out)
static __device__ __nv_bfloat16 g_Al[MTOT * EMB];        // GEMM A lo
static __device__ __nv_bfloat16 g_WhQ[3 * EMB * EMB];    // W_qkv^T hi  [N=3072,K=1024]
static __device__ __nv_bfloat16 g_WlQ[3 * EMB * EMB];
static __device__ __nv_bfloat16 g_WhP[EMB * EMB];        // W_proj^T hi [N=1024,K=1024]
static __device__ __nv_bfloat16 g_WlP[EMB * EMB];

static __device__ __nv_bfloat16 g_Qh[BATCH * NH * S_LEN * HD];  // Q hi (pre-scaled)
static __device__ __nv_bfloat16 g_Ql[BATCH * NH * S_LEN * HD];
static __device__ __nv_bfloat16 g_Kh[BATCH * NH * S_LEN * HD];
static __device__ __nv_bfloat16 g_Kl[BATCH * NH * S_LEN * HD];
static __device__ __nv_bfloat16 g_Vh[BATCH * NH * S_LEN * HD];
static __device__ __nv_bfloat16 g_Vl[BATCH * NH * S_LEN * HD];

// ---------------------------------------------------------------------------
// Portable PTX helpers (compute_100-safe)
// ---------------------------------------------------------------------------
static __device__ __forceinline__ uint32_t smem_u32(const void* p) {
    uint32_t a;
    asm("{ .reg .u64 t; cvta.to.shared.u64 t, %1; cvt.u32.u64 %0, t; }" : "=r"(a) : "l"(p));
    return a;
}
static __device__ __forceinline__ void cp_async16(uint32_t dst, const void* src) {
    asm volatile("cp.async.cg.shared.global [%0], [%1], 16;" :: "r"(dst), "l"(src) : "memory");
}
#define CP_COMMIT() asm volatile("cp.async.commit_group;" ::: "memory")
#define CP_WAIT1()  asm volatile("cp.async.wait_group 1;" ::: "memory")
#define CP_WAIT2()  asm volatile("cp.async.wait_group 2;" ::: "memory")

static __device__ __forceinline__ void ldmatrix_x4(uint32_t* r, uint32_t addr) {
    asm volatile("ldmatrix.sync.aligned.m8n8.x4.shared.b16 {%0,%1,%2,%3}, [%4];"
                 : "=r"(r[0]), "=r"(r[1]), "=r"(r[2]), "=r"(r[3]) : "r"(addr));
}
static __device__ __forceinline__ void ldmatrix_x2(uint32_t* r, uint32_t addr) {
    asm volatile("ldmatrix.sync.aligned.m8n8.x2.shared.b16 {%0,%1}, [%2];"
                 : "=r"(r[0]), "=r"(r[1]) : "r"(addr));
}
static __device__ __forceinline__ void ldmatrix_x2_trans(uint32_t* r, uint32_t addr) {
    asm volatile("ldmatrix.sync.aligned.m8n8.x2.trans.shared.b16 {%0,%1}, [%2];"
                 : "=r"(r[0]), "=r"(r[1]) : "r"(addr));
}
static __device__ __forceinline__ void mma_bf16(float* d, const uint32_t* a, const uint32_t* b) {
    asm volatile("mma.sync.aligned.m16n8k16.row.col.f32.bf16.bf16.f32 "
                 "{%0,%1,%2,%3}, {%4,%5,%6,%7}, {%8,%9}, {%0,%1,%2,%3};"
                 : "+f"(d[0]), "+f"(d[1]), "+f"(d[2]), "+f"(d[3])
                 : "r"(a[0]), "r"(a[1]), "r"(a[2]), "r"(a[3]), "r"(b[0]), "r"(b[1]));
}
static __device__ __forceinline__ float ex2f(float x) {
    float y;
    asm("ex2.approx.ftz.f32 %0, %1;" : "=f"(y) : "f"(x));
    return y;
}

// ---------------------------------------------------------------------------
// Pre-processing kernels
// ---------------------------------------------------------------------------
__global__ void conv_act_kernel(const float4* __restrict__ in,
                                uint2* __restrict__ hi, uint2* __restrict__ lo, int n4)
{
    int i = blockIdx.x * 256 + threadIdx.x;
    if (i >= n4) return;
    float4 v = in[i];
    float a[4] = {v.x, v.y, v.z, v.w};
    uint32_t H[2] = {0, 0}, L[2] = {0, 0};
#pragma unroll
    for (int c = 0; c < 4; c++) {
        __nv_bfloat16 h = __float2bfloat16(a[c]);
        __nv_bfloat16 l = __float2bfloat16(a[c] - __bfloat162float(h));
        H[c >> 1] |= (uint32_t)__bfloat16_as_ushort(h) << ((c & 1) * 16);
        L[c >> 1] |= (uint32_t)__bfloat16_as_ushort(l) << ((c & 1) * 16);
    }
    hi[i] = make_uint2(H[0], H[1]);
    lo[i] = make_uint2(L[0], L[1]);
}

__global__ void conv_wT_kernel(const float* __restrict__ W,
                               __nv_bfloat16* __restrict__ Th,
                               __nv_bfloat16* __restrict__ Tl, int Kd, int Nd)
{
    __shared__ float t[32][33];
    const int n0 = blockIdx.x * 32, k0 = blockIdx.y * 32;
    const int tx = threadIdx.x, ty = threadIdx.y;
#pragma unroll
    for (int j = 0; j < 32; j += 8)
        t[ty + j][tx] = W[(size_t)(k0 + ty + j) * Nd + n0 + tx];
    __syncthreads();
#pragma unroll
    for (int j = 0; j < 32; j += 8) {
        float v = t[tx][ty + j];
        __nv_bfloat16 h = __float2bfloat16(v);
        __nv_bfloat16 l = __float2bfloat16(v - __bfloat162float(h));
        size_t o = (size_t)(n0 + ty + j) * Kd + k0 + tx;
        Th[o] = h;
        Tl[o] = l;
    }
}

// ---------------------------------------------------------------------------
// bf16x3 mma.sync GEMM — R4 skeleton (best measured): 128x128 tile, 8 warps
// (64x32 each), BK=32, pitch-40 smem, 2-stage cp.async pipeline, 2 CTAs/SM.
// NEW: MMA issue order round-robins accumulators (RAW distance 1 -> 4).
// mode 0: fp32 C (+bias). mode 1: QKV epilogue -> hi/lo bf16 K/Q/V
// in [B,H,S,D]; Q pre-scaled by 0.125*log2(e).
// ---------------------------------------------------------------------------
#define BK      32
#define PITCH   40                       // bf16 units (80 B rows, conflict-free)
#define TILE_B  (128 * PITCH * 2)        // 10240 B
#define STAGE_B (4 * TILE_B)             // 40960 B (Ah, Al, Bh, Bl)
#define GEMM_SMEM (2 * STAGE_B)          // 81920 B

#define QSCALE  0.1803368801111244f      // 0.125 * log2(e)

static __device__ __forceinline__ void issue_stage(
    uint32_t sstage, const __nv_bfloat16* __restrict__ Ahg,
    const __nv_bfloat16* __restrict__ Alg, const __nv_bfloat16* __restrict__ Bhg,
    const __nv_bfloat16* __restrict__ Blg,
    int bm0, int bn0, int K, int kof, int tid)
{
    const int r = tid >> 1;               // 0..127
    const int c0 = (tid & 1) * 2;         // chunk pair
#pragma unroll
    for (int cc = 0; cc < 2; cc++) {
        const int c = c0 + cc;
        const uint32_t so = (uint32_t)(r * (PITCH * 2) + c * 16);
        const size_t ga = (size_t)(bm0 + r) * K + kof + c * 8;
        const size_t gb = (size_t)(bn0 + r) * K + kof + c * 8;
        cp_async16(sstage + 0 * TILE_B + so, Ahg + ga);
        cp_async16(sstage + 1 * TILE_B + so, Alg + ga);
        cp_async16(sstage + 2 * TILE_B + so, Bhg + gb);
        cp_async16(sstage + 3 * TILE_B + so, Blg + gb);
    }
}

__global__ __launch_bounds__(256, 2)
void gemm_bf16x3_kernel(
    const __nv_bfloat16* __restrict__ Ahg, const __nv_bfloat16* __restrict__ Alg,
    const __nv_bfloat16* __restrict__ Bhg, const __nv_bfloat16* __restrict__ Blg,
    const float* __restrict__ bias, float* __restrict__ C,
    int M, int N, int K, int mode,
    __nv_bfloat16* __restrict__ kh, __nv_bfloat16* __restrict__ kl,
    __nv_bfloat16* __restrict__ qh, __nv_bfloat16* __restrict__ ql,
    __nv_bfloat16* __restrict__ vh, __nv_bfloat16* __restrict__ vl)
{
    extern __shared__ char smem[];
    const uint32_t sbase = smem_u32(smem);
    const int tid  = threadIdx.x;
    const int wid  = tid >> 5;
    const int lane = tid & 31;
    const int bm0 = blockIdx.y * 128;
    const int bn0 = blockIdx.x * 128;

    const int wm = (wid & 1) * 64;
    const int wn = (wid >> 1) * 32;

    float acc[4][4][4];
#pragma unroll
    for (int i = 0; i < 4; i++)
#pragma unroll
        for (int j = 0; j < 4; j++)
#pragma unroll
            for (int c = 0; c < 4; c++) acc[i][j][c] = 0.f;

    const int nk = K / BK;   // 32

    issue_stage(sbase + 0 * STAGE_B, Ahg, Alg, Bhg, Blg, bm0, bn0, K, 0, tid);
    CP_COMMIT();
    issue_stage(sbase + 1 * STAGE_B, Ahg, Alg, Bhg, Blg, bm0, bn0, K, BK, tid);
    CP_COMMIT();

    const uint32_t a_off = (uint32_t)(lane & 15) * (PITCH * 2) + (uint32_t)(lane >> 4) * 16;
    const uint32_t b_off = (uint32_t)(lane & 7) * (PITCH * 2) + (uint32_t)((lane >> 3) & 1) * 16;

    for (int it = 0; it < nk; it++) {
        CP_WAIT1();
        __syncthreads();
        const uint32_t st = sbase + (it & 1) * STAGE_B;
#pragma unroll
        for (int ks = 0; ks < 2; ks++) {
            uint32_t ah[4][4], al[4][4];
#pragma unroll
            for (int i = 0; i < 4; i++) {
                const uint32_t ro = st + (uint32_t)(wm + i * 16) * (PITCH * 2)
                                  + (uint32_t)(ks * 32) + a_off;
                ldmatrix_x4(ah[i], ro);
                ldmatrix_x4(al[i], ro + TILE_B);
            }
#pragma unroll
            for (int j = 0; j < 4; j++) {
                uint32_t bh2[2], bl2[2];
                const uint32_t ro = st + 2 * TILE_B + (uint32_t)(wn + j * 8) * (PITCH * 2)
                                  + (uint32_t)(ks * 32) + b_off;
                ldmatrix_x2(bh2, ro);
                ldmatrix_x2(bl2, ro + TILE_B);
                // round-robin accumulators: RAW distance 4 instead of 1
#pragma unroll
                for (int i = 0; i < 4; i++) mma_bf16(acc[i][j], ah[i], bh2);
#pragma unroll
                for (int i = 0; i < 4; i++) mma_bf16(acc[i][j], ah[i], bl2);
#pragma unroll
                for (int i = 0; i < 4; i++) mma_bf16(acc[i][j], al[i], bh2);
            }
        }
        __syncthreads();
        if (it + 2 < nk)
            issue_stage(st, Ahg, Alg, Bhg, Blg, bm0, bn0, K, (it + 2) * BK, tid);
        CP_COMMIT();
    }

    const int lr = lane >> 2;
    const int lc = (lane & 3) * 2;
#pragma unroll
    for (int i = 0; i < 4; i++) {
#pragma unroll
        for (int j = 0; j < 4; j++) {
            const int col = bn0 + wn + j * 8 + lc;
            const float bx = bias[col], by = bias[col + 1];
#pragma unroll
            for (int h2 = 0; h2 < 2; h2++) {
                const int row = bm0 + wm + i * 16 + lr + h2 * 8;
                float vx = acc[i][j][h2 * 2 + 0] + bx;
                float vy = acc[i][j][h2 * 2 + 1] + by;
                if (mode == 0) {
                    float2 v = make_float2(vx, vy);
                    *(float2*)&C[(size_t)row * N + col] = v;
                } else {
                    const int sec = col >> 10;
                    if (sec == 1) { vx *= QSCALE; vy *= QSCALE; }
                    const int hh  = (col >> 6) & 15;
                    const int d   = col & 63;
                    const int b_  = row >> 11;
                    const int s   = row & 2047;
                    const size_t off = (((size_t)(b_ * NH + hh)) * S_LEN + s) * HD + d;
                    __nv_bfloat16 hx = __float2bfloat16(vx);
                    __nv_bfloat16 hy = __float2bfloat16(vy);
                    __nv_bfloat16 lx = __float2bfloat16(vx - __bfloat162float(hx));
                    __nv_bfloat16 ly = __float2bfloat16(vy - __bfloat162float(hy));
                    __nv_bfloat16* dh = (sec == 0) ? kh : ((sec == 1) ? qh : vh);
                    __nv_bfloat16* dl = (sec == 0) ? kl : ((sec == 1) ? ql : vl);
                    __nv_bfloat162 hv; hv.x = hx; hv.y = hy;
                    __nv_bfloat162 lv; lv.x = lx; lv.y = ly;
                    *(__nv_bfloat162*)&dh[off] = hv;
                    *(__nv_bfloat162*)&dl[off] = lv;
                }
            }
        }
    }
}

// ---------------------------------------------------------------------------
// Flash attention (causal) on mma.sync, bf16x3 precision.
// Block: 128 q-rows x (B*H). 8 warps, each warp m16 x n64.
// 64-key KV tiles, 3-stage cp.async pipeline, one sync per tile.
// NEW: paired-j MMA interleaving to break accumulator RAW chains.
// ---------------------------------------------------------------------------
#define KPITCH 144                       // bytes per 64-dim row (72 bf16)
#define QT (128 * KPITCH)                // 18432 B per Q component
#define CT (64 * KPITCH)                 // 9216 B per KV component tile
#define KVNST 3
#define ATT_SMEM (2 * QT + KVNST * 4 * CT)   // 147456 B

static __device__ __forceinline__ void issue_kv(
    uint32_t dst, const __nv_bfloat16* __restrict__ Kh, const __nv_bfloat16* __restrict__ Kl,
    const __nv_bfloat16* __restrict__ Vh, const __nv_bfloat16* __restrict__ Vl,
    size_t gbase, int k0, int tid)
{
    const int r = tid >> 2;
    const int c = tid & 3;
    const size_t g = gbase + (size_t)(k0 + r) * HD;
#pragma unroll
    for (int cc = 0; cc < 2; cc++) {
        const int ch = c + cc * 4;
        const uint32_t so = (uint32_t)(r * KPITCH + ch * 16);
        cp_async16(dst + 0 * CT + so, Kh + g + ch * 8);
        cp_async16(dst + 1 * CT + so, Kl + g + ch * 8);
        cp_async16(dst + 2 * CT + so, Vh + g + ch * 8);
        cp_async16(dst + 3 * CT + so, Vl + g + ch * 8);
    }
}

__global__ __launch_bounds__(256)
void attn_mma_kernel(
    const __nv_bfloat16* __restrict__ Qh, const __nv_bfloat16* __restrict__ Ql,
    const __nv_bfloat16* __restrict__ Kh, const __nv_bfloat16* __restrict__ Kl,
    const __nv_bfloat16* __restrict__ Vh, const __nv_bfloat16* __restrict__ Vl,
    __nv_bfloat16* __restrict__ Oh, __nv_bfloat16* __restrict__ Ol)
{
    extern __shared__ char smem[];
    const uint32_t sb = smem_u32(smem);
    const uint32_t sQ = sb;                  // Qh tile, Ql at +QT
    const uint32_t sKV = sb + 2 * QT;        // KVNST stages of 4*CT

    const int tid = threadIdx.x;
    const int lane = tid & 31;
    const int w = tid >> 5;
    const int qb = (int)gridDim.x - 1 - (int)blockIdx.x;   // long blocks first
    const int bh = blockIdx.y;
    const int q0 = qb * 128;
    const size_t base = (size_t)bh * S_LEN * HD;

    // load Q hi/lo tile (group 0)
    {
        const int r = tid >> 1;
        const int c0 = (tid & 1) * 4;
#pragma unroll
        for (int c = c0; c < c0 + 4; c++) {
            const uint32_t so = (uint32_t)(r * KPITCH + c * 16);
            const size_t g = base + (size_t)(q0 + r) * HD + c * 8;
            cp_async16(sQ + so, Qh + g);
            cp_async16(sQ + QT + so, Ql + g);
        }
    }
    CP_COMMIT();

    const int nt = 2 * qb + 2;
    issue_kv(sKV + 0 * 4 * CT, Kh, Kl, Vh, Vl, base, 0, tid);
    CP_COMMIT();
    if (nt > 1) {
        issue_kv(sKV + 1 * 4 * CT, Kh, Kl, Vh, Vl, base, 64, tid);
    }
    CP_COMMIT();

    CP_WAIT2();          // Q done (kv0, kv1 may be pending)
    __syncthreads();

    // resident Q fragments
    const int wm = w * 16;
    uint32_t qfh[4][4], qfl[4][4];
    {
        const uint32_t ab = sQ + (uint32_t)((wm + (lane & 15)) * KPITCH + (lane >> 4) * 16);
#pragma unroll
        for (int kk = 0; kk < 4; kk++) {
            ldmatrix_x4(qfh[kk], ab + kk * 32);
            ldmatrix_x4(qfl[kk], ab + QT + kk * 32);
        }
    }

    float o[8][4];
#pragma unroll
    for (int j = 0; j < 8; j++)
#pragma unroll
        for (int c = 0; c < 4; c++) o[j][c] = 0.f;
    float m0 = -1e30f, m1 = -1e30f, l0 = 0.f, l1 = 0.f;

    int stage = 0, wstage = 2 % KVNST;
    for (int it = 0; it < nt; it++) {
        CP_WAIT1();          // kv(it) done (<=1 pending: kv(it+1))
        __syncthreads();     // visible; all warps finished stage (it-1)
        if (it + 2 < nt) {
            issue_kv(sKV + wstage * 4 * CT, Kh, Kl, Vh, Vl, base, (it + 2) * 64, tid);
            CP_COMMIT();
        } else {
            CP_COMMIT();     // keep group counts uniform
        }

        const int k0 = it * 64;
        const bool active = (k0 <= q0 + wm + 15);
        if (active) {
            const uint32_t st = sKV + stage * 4 * CT;

            // ---- S = Q K^T (bf16x3), per warp m16 x n64, paired-j issue ----
            float s[8][4];
#pragma unroll
            for (int j = 0; j < 8; j++)
#pragma unroll
                for (int c = 0; c < 4; c++) s[j][c] = 0.f;

            const uint32_t kb_ = st + (uint32_t)((lane & 7) * KPITCH + ((lane >> 3) & 1) * 16);
#pragma unroll
            for (int kk = 0; kk < 4; kk++) {
#pragma unroll
                for (int jp = 0; jp < 4; jp++) {
                    const int j0 = jp * 2, j1 = j0 + 1;
                    uint32_t bh2a[2], bl2a[2], bh2b[2], bl2b[2];
                    const uint32_t ro0 = kb_ + (uint32_t)(j0 * 8 * KPITCH + kk * 32);
                    const uint32_t ro1 = kb_ + (uint32_t)(j1 * 8 * KPITCH + kk * 32);
                    ldmatrix_x2(bh2a, ro0);
                    ldmatrix_x2(bl2a, ro0 + CT);
                    ldmatrix_x2(bh2b, ro1);
                    ldmatrix_x2(bl2b, ro1 + CT);
                    mma_bf16(s[j0], qfh[kk], bh2a);
                    mma_bf16(s[j1], qfh[kk], bh2b);
                    mma_bf16(s[j0], qfh[kk], bl2a);
                    mma_bf16(s[j1], qfh[kk], bl2b);
                    mma_bf16(s[j0], qfl[kk], bh2a);
                    mma_bf16(s[j1], qfl[kk], bh2b);
                }
            }

            // ---- causal mask (log2 domain; Q pre-scaled) ----
            if (k0 + 63 > q0 + wm) {
#pragma unroll
                for (int j = 0; j < 8; j++)
#pragma unroll
                    for (int c = 0; c < 4; c++) {
                        const int kc = k0 + j * 8 + 2 * (lane & 3) + (c & 1);
                        const int rq = q0 + wm + (lane >> 2) + (c >> 1) * 8;
                        if (kc > rq) s[j][c] = -1e30f;
                    }
            }

            // ---- online softmax (exp2 domain) ----
            float mx0 = -1e30f, mx1 = -1e30f;
#pragma unroll
            for (int j = 0; j < 8; j++) {
                mx0 = fmaxf(mx0, fmaxf(s[j][0], s[j][1]));
                mx1 = fmaxf(mx1, fmaxf(s[j][2], s[j][3]));
            }
            mx0 = fmaxf(mx0, __shfl_xor_sync(0xffffffffu, mx0, 1));
            mx0 = fmaxf(mx0, __shfl_xor_sync(0xffffffffu, mx0, 2));
            mx1 = fmaxf(mx1, __shfl_xor_sync(0xffffffffu, mx1, 1));
            mx1 = fmaxf(mx1, __shfl_xor_sync(0xffffffffu, mx1, 2));

            const float mn0 = fmaxf(m0, mx0);
            const float mn1 = fmaxf(m1, mx1);
            const float f0 = ex2f(m0 - mn0);
            const float f1 = ex2f(m1 - mn1);
            m0 = mn0; m1 = mn1;

            float sum0 = 0.f, sum1 = 0.f;
#pragma unroll
            for (int j = 0; j < 8; j++) {
                s[j][0] = ex2f(s[j][0] - mn0);
                s[j][1] = ex2f(s[j][1] - mn0);
                s[j][2] = ex2f(s[j][2] - mn1);
                s[j][3] = ex2f(s[j][3] - mn1);
                sum0 += s[j][0] + s[j][1];
                sum1 += s[j][2] + s[j][3];
            }
            sum0 += __shfl_xor_sync(0xffffffffu, sum0, 1);
            sum0 += __shfl_xor_sync(0xffffffffu, sum0, 2);
            sum1 += __shfl_xor_sync(0xffffffffu, sum1, 1);
            sum1 += __shfl_xor_sync(0xffffffffu, sum1, 2);
            l0 = l0 * f0 + sum0;
            l1 = l1 * f1 + sum1;

#pragma unroll
            for (int j = 0; j < 8; j++) {
                o[j][0] *= f0; o[j][1] *= f0;
                o[j][2] *= f1; o[j][3] *= f1;
            }

            // ---- O += P V (bf16x3), paired-jd issue ----
            const uint32_t vb_ = st + 2 * CT + (uint32_t)((lane & 15) * KPITCH);
#pragma unroll
            for (int t = 0; t < 4; t++) {
                uint32_t ph[4], pl[4];
#pragma unroll
                for (int half = 0; half < 2; half++) {
                    const float* sp = s[2 * t + half];
                    __nv_bfloat162 h01 = __float22bfloat162_rn(make_float2(sp[0], sp[1]));
                    __nv_bfloat162 h23 = __float22bfloat162_rn(make_float2(sp[2], sp[3]));
                    __nv_bfloat162 r01 = __float22bfloat162_rn(make_float2(
                        sp[0] - __bfloat162float(h01.x), sp[1] - __bfloat162float(h01.y)));
                    __nv_bfloat162 r23 = __float22bfloat162_rn(make_float2(
                        sp[2] - __bfloat162float(h23.x), sp[3] - __bfloat162float(h23.y)));
                    ph[2 * half + 0] = *(uint32_t*)&h01;
                    ph[2 * half + 1] = *(uint32_t*)&h23;
                    pl[2 * half + 0] = *(uint32_t*)&r01;
                    pl[2 * half + 1] = *(uint32_t*)&r23;
                }
                uint32_t pa_h[4] = {ph[0], ph[1], ph[2], ph[3]};
                uint32_t pa_l[4] = {pl[0], pl[1], pl[2], pl[3]};
#pragma unroll
                for (int jq = 0; jq < 4; jq++) {
                    const int jd0 = jq * 2, jd1 = jd0 + 1;
                    uint32_t vh2a[2], vl2a[2], vh2b[2], vl2b[2];
                    const uint32_t vo0 = vb_ + (uint32_t)(16 * t * KPITCH + jd0 * 16);
                    const uint32_t vo1 = vb_ + (uint32_t)(16 * t * KPITCH + jd1 * 16);
                    ldmatrix_x2_trans(vh2a, vo0);
                    ldmatrix_x2_trans(vl2a, vo0 + CT);
                    ldmatrix_x2_trans(vh2b, vo1);
                    ldmatrix_x2_trans(vl2b, vo1 + CT);
                    mma_bf16(o[jd0], pa_h, vh2a);
                    mma_bf16(o[jd1], pa_h, vh2b);
                    mma_bf16(o[jd0], pa_h, vl2a);
                    mma_bf16(o[jd1], pa_h, vl2b);
                    mma_bf16(o[jd0], pa_l, vh2a);
                    mma_bf16(o[jd1], pa_l, vh2b);
                }
            }
        }

        if (++stage == KVNST) stage = 0;
        if (++wstage == KVNST) wstage = 0;
    }

    // ---- epilogue: normalize, split hi/lo, write [M,E] bf16 ----
    const int b = bh >> 4;
    const int h = bh & 15;
    const float inv0 = 1.0f / l0;
    const float inv1 = 1.0f / l1;
    const int r0 = b * S_LEN + q0 + wm + (lane >> 2);
    const int colb = h * HD + 2 * (lane & 3);
#pragma unroll
    for (int jd = 0; jd < 8; jd++) {
        const int col = colb + jd * 8;
#pragma unroll
        for (int h2 = 0; h2 < 2; h2++) {
            const float inv = h2 ? inv1 : inv0;
            const float vx = o[jd][h2 * 2 + 0] * inv;
            const float vy = o[jd][h2 * 2 + 1] * inv;
            const size_t off = (size_t)(r0 + h2 * 8) * EMB + col;
            __nv_bfloat162 hv = __float22bfloat162_rn(make_float2(vx, vy));
            __nv_bfloat162 lv = __float22bfloat162_rn(make_float2(
                vx - __bfloat162float(hv.x), vy - __bfloat162float(hv.y)));
            *(__nv_bfloat162*)&Oh[off] = hv;
            *(__nv_bfloat162*)&Ol[off] = lv;
        }
    }
}

// ---------------------------------------------------------------------------
// Launch
// ---------------------------------------------------------------------------
extern "C" void kernel_launch(void* const* d_in, const int* in_sizes, int n_in,
                              void* d_out, int out_size)
{
    const float* x      = (const float*)d_in[0];
    const float* W_qkv  = (const float*)d_in[1];
    const float* b_qkv  = (const float*)d_in[2];
    const float* W_proj = (const float*)d_in[3];
    const float* b_proj = (const float*)d_in[4];
    float* out = (float*)d_out;

    __nv_bfloat16 *Ah, *Al, *WhQ, *WlQ, *WhP, *WlP;
    __nv_bfloat16 *Qh, *Ql, *Kh, *Kl, *Vh, *Vl;
    cudaGetSymbolAddress((void**)&Ah, g_Ah);
    cudaGetSymbolAddress((void**)&Al, g_Al);
    cudaGetSymbolAddress((void**)&WhQ, g_WhQ);
    cudaGetSymbolAddress((void**)&WlQ, g_WlQ);
    cudaGetSymbolAddress((void**)&WhP, g_WhP);
    cudaGetSymbolAddress((void**)&WlP, g_WlP);
    cudaGetSymbolAddress((void**)&Qh, g_Qh);
    cudaGetSymbolAddress((void**)&Ql, g_Ql);
    cudaGetSymbolAddress((void**)&Kh, g_Kh);
    cudaGetSymbolAddress((void**)&Kl, g_Kl);
    cudaGetSymbolAddress((void**)&Vh, g_Vh);
    cudaGetSymbolAddress((void**)&Vl, g_Vl);

    cudaFuncSetAttribute(gemm_bf16x3_kernel,
                         cudaFuncAttributeMaxDynamicSharedMemorySize, GEMM_SMEM);
    cudaFuncSetAttribute(attn_mma_kernel,
                         cudaFuncAttributeMaxDynamicSharedMemorySize, ATT_SMEM);

    // 0) pre-split weights (transposed) and input activations
    {
        dim3 blk(32, 8);
        conv_wT_kernel<<<dim3(3 * EMB / 32, EMB / 32), blk>>>(W_qkv, WhQ, WlQ, EMB, 3 * EMB);
        conv_wT_kernel<<<dim3(EMB / 32, EMB / 32), blk>>>(W_proj, WhP, WlP, EMB, EMB);
        const int n4 = MTOT * EMB / 4;
        conv_act_kernel<<<n4 / 256, 256>>>((const float4*)x, (uint2*)Ah, (uint2*)Al, n4);
    }

    // 1) QKV projection -> hi/lo bf16 K/Q/V in [B,H,S,D] (Q pre-scaled)
    gemm_bf16x3_kernel<<<dim3(3 * EMB / 128, MTOT / 128), 256, GEMM_SMEM>>>(
        Ah, Al, WhQ, WlQ, b_qkv, nullptr, MTOT, 3 * EMB, EMB, 1,
        Kh, Kl, Qh, Ql, Vh, Vl);

    // 2) fused causal flash attention (tensor cores, bf16x3) -> Ah/Al
    attn_mma_kernel<<<dim3(S_LEN / 128, BATCH * NH), 256, ATT_SMEM>>>(
        Qh, Ql, Kh, Kl, Vh, Vl, Ah, Al);

    // 3) output projection -> fp32 out
    gemm_bf16x3_kernel<<<dim3(EMB / 128, MTOT / 128), 256, GEMM_SMEM>>>(
        Ah, Al, WhP, WlP, b_proj, out, MTOT, EMB, EMB, 0,
        nullptr, nullptr, nullptr, nullptr, nullptr, nullptr);
}

// round 9
// speedup vs baseline: 1.2060x; 1.2060x over previous
#include <cuda_runtime.h>
#include <cuda_bf16.h>
#include <cuda_fp16.h>
#include <cstdint>

#define BATCH 4
#define S_LEN 2048
#define EMB   1024
#define NH    16
#define HD    64
#define MTOT  (BATCH * S_LEN)   // 8192

// ---------------------------------------------------------------------------
// Device-global scratch (allocation-free requirement)
// ---------------------------------------------------------------------------
static __device__ __half g_Ah[MTOT * EMB];               // GEMM A hi (fp16)
static __device__ __half g_Al[MTOT * EMB];               // GEMM A lo (fp16)
static __device__ __half g_WQ[3 * EMB * EMB];            // W_qkv^T fp16 [N=3072,K=1024]
static __device__ __half g_WP[EMB * EMB];                // W_proj^T fp16 [N=1024,K=1024]

static __device__ __nv_bfloat16 g_Qh[BATCH * NH * S_LEN * HD];  // Q hi (pre-scaled, bf16)
static __device__ __nv_bfloat16 g_Ql[BATCH * NH * S_LEN * HD];
static __device__ __nv_bfloat16 g_Kh[BATCH * NH * S_LEN * HD];
static __device__ __nv_bfloat16 g_Kl[BATCH * NH * S_LEN * HD];
static __device__ __nv_bfloat16 g_Vh[BATCH * NH * S_LEN * HD];
static __device__ __nv_bfloat16 g_Vl[BATCH * NH * S_LEN * HD];

// ---------------------------------------------------------------------------
// Portable PTX helpers (compute_100-safe)
// ---------------------------------------------------------------------------
static __device__ __forceinline__ uint32_t smem_u32(const void* p) {
    uint32_t a;
    asm("{ .reg .u64 t; cvta.to.shared.u64 t, %1; cvt.u32.u64 %0, t; }" : "=r"(a) : "l"(p));
    return a;
}
static __device__ __forceinline__ void cp_async16(uint32_t dst, const void* src) {
    asm volatile("cp.async.cg.shared.global [%0], [%1], 16;" :: "r"(dst), "l"(src) : "memory");
}
#define CP_COMMIT() asm volatile("cp.async.commit_group;" ::: "memory")
#define CP_WAIT1()  asm volatile("cp.async.wait_group 1;" ::: "memory")
#define CP_WAIT2()  asm volatile("cp.async.wait_group 2;" ::: "memory")

static __device__ __forceinline__ void ldmatrix_x4(uint32_t* r, uint32_t addr) {
    asm volatile("ldmatrix.sync.aligned.m8n8.x4.shared.b16 {%0,%1,%2,%3}, [%4];"
                 : "=r"(r[0]), "=r"(r[1]), "=r"(r[2]), "=r"(r[3]) : "r"(addr));
}
static __device__ __forceinline__ void ldmatrix_x2(uint32_t* r, uint32_t addr) {
    asm volatile("ldmatrix.sync.aligned.m8n8.x2.shared.b16 {%0,%1}, [%2];"
                 : "=r"(r[0]), "=r"(r[1]) : "r"(addr));
}
static __device__ __forceinline__ void ldmatrix_x2_trans(uint32_t* r, uint32_t addr) {
    asm volatile("ldmatrix.sync.aligned.m8n8.x2.trans.shared.b16 {%0,%1}, [%2];"
                 : "=r"(r[0]), "=r"(r[1]) : "r"(addr));
}
static __device__ __forceinline__ void mma_bf16(float* d, const uint32_t* a, const uint32_t* b) {
    asm volatile("mma.sync.aligned.m16n8k16.row.col.f32.bf16.bf16.f32 "
                 "{%0,%1,%2,%3}, {%4,%5,%6,%7}, {%8,%9}, {%0,%1,%2,%3};"
                 : "+f"(d[0]), "+f"(d[1]), "+f"(d[2]), "+f"(d[3])
                 : "r"(a[0]), "r"(a[1]), "r"(a[2]), "r"(a[3]), "r"(b[0]), "r"(b[1]));
}
static __device__ __forceinline__ void mma_f16(float* d, const uint32_t* a, const uint32_t* b) {
    asm volatile("mma.sync.aligned.m16n8k16.row.col.f32.f16.f16.f32 "
                 "{%0,%1,%2,%3}, {%4,%5,%6,%7}, {%8,%9}, {%0,%1,%2,%3};"
                 : "+f"(d[0]), "+f"(d[1]), "+f"(d[2]), "+f"(d[3])
                 : "r"(a[0]), "r"(a[1]), "r"(a[2]), "r"(a[3]), "r"(b[0]), "r"(b[1]));
}
static __device__ __forceinline__ float ex2f(float x) {
    float y;
    asm("ex2.approx.ftz.f32 %0, %1;" : "=f"(y) : "f"(x));
    return y;
}

// ---------------------------------------------------------------------------
// Pre-processing kernels (fp16 for GEMM operands)
// ---------------------------------------------------------------------------
__global__ void conv_act_kernel(const float4* __restrict__ in,
                                __half2* __restrict__ hi, __half2* __restrict__ lo, int n4)
{
    int i = blockIdx.x * 256 + threadIdx.x;
    if (i >= n4) return;
    float4 v = in[i];
    __half2 h0 = __floats2half2_rn(v.x, v.y);
    __half2 h1 = __floats2half2_rn(v.z, v.w);
    __half2 l0 = __floats2half2_rn(v.x - __half2float(__low2half(h0)),
                                   v.y - __half2float(__high2half(h0)));
    __half2 l1 = __floats2half2_rn(v.z - __half2float(__low2half(h1)),
                                   v.w - __half2float(__high2half(h1)));
    hi[i * 2 + 0] = h0;
    hi[i * 2 + 1] = h1;
    lo[i * 2 + 0] = l0;
    lo[i * 2 + 1] = l1;
}

// W [K,N] fp32 -> W^T [N,K] fp16 (tiled transpose, single precision level)
__global__ void conv_wT_kernel(const float* __restrict__ W,
                               __half* __restrict__ Th, int Kd, int Nd)
{
    __shared__ float t[32][33];
    const int n0 = blockIdx.x * 32, k0 = blockIdx.y * 32;
    const int tx = threadIdx.x, ty = threadIdx.y;
#pragma unroll
    for (int j = 0; j < 32; j += 8)
        t[ty + j][tx] = W[(size_t)(k0 + ty + j) * Nd + n0 + tx];
    __syncthreads();
#pragma unroll
    for (int j = 0; j < 32; j += 8) {
        float v = t[tx][ty + j];
        Th[(size_t)(n0 + ty + j) * Kd + k0 + tx] = __float2half_rn(v);
    }
}

// ---------------------------------------------------------------------------
// fp16 2-product mma.sync GEMM — R4 skeleton: 128x128 tile, 8 warps (64x32),
// BK=32, pitch-40 smem, 2-stage cp.async pipeline, 2 CTAs/SM.
// D = Ah*W + Al*W (A exact as fp16 hi+lo; W single fp16) -> 2 MMAs per product
// group instead of bf16x3's 3.
// mode 0: fp32 C (+bias). mode 1: QKV epilogue -> hi/lo bf16 K/Q/V
// in [B,H,S,D]; Q pre-scaled by 0.125*log2(e).
// ---------------------------------------------------------------------------
#define BK      32
#define PITCH   40                       // fp16 units (80 B rows, conflict-free)
#define TILE_B  (128 * PITCH * 2)        // 10240 B
#define STAGE_B (3 * TILE_B)             // 30720 B (Ah, Al, W)
#define GEMM_SMEM (2 * STAGE_B)          // 61440 B

#define QSCALE  0.1803368801111244f      // 0.125 * log2(e)

static __device__ __forceinline__ void issue_stage(
    uint32_t sstage, const __half* __restrict__ Ahg,
    const __half* __restrict__ Alg, const __half* __restrict__ Bg,
    int bm0, int bn0, int K, int kof, int tid)
{
    const int r = tid >> 1;               // 0..127
    const int c0 = (tid & 1) * 2;         // chunk pair
#pragma unroll
    for (int cc = 0; cc < 2; cc++) {
        const int c = c0 + cc;
        const uint32_t so = (uint32_t)(r * (PITCH * 2) + c * 16);
        const size_t ga = (size_t)(bm0 + r) * K + kof + c * 8;
        const size_t gb = (size_t)(bn0 + r) * K + kof + c * 8;
        cp_async16(sstage + 0 * TILE_B + so, Ahg + ga);
        cp_async16(sstage + 1 * TILE_B + so, Alg + ga);
        cp_async16(sstage + 2 * TILE_B + so, Bg + gb);
    }
}

__global__ __launch_bounds__(256, 2)
void gemm_f16x2_kernel(
    const __half* __restrict__ Ahg, const __half* __restrict__ Alg,
    const __half* __restrict__ Bg,
    const float* __restrict__ bias, float* __restrict__ C,
    int M, int N, int K, int mode,
    __nv_bfloat16* __restrict__ kh, __nv_bfloat16* __restrict__ kl,
    __nv_bfloat16* __restrict__ qh, __nv_bfloat16* __restrict__ ql,
    __nv_bfloat16* __restrict__ vh, __nv_bfloat16* __restrict__ vl)
{
    extern __shared__ char smem[];
    const uint32_t sbase = smem_u32(smem);
    const int tid  = threadIdx.x;
    const int wid  = tid >> 5;
    const int lane = tid & 31;
    const int bm0 = blockIdx.y * 128;
    const int bn0 = blockIdx.x * 128;

    const int wm = (wid & 1) * 64;
    const int wn = (wid >> 1) * 32;

    float acc[4][4][4];
#pragma unroll
    for (int i = 0; i < 4; i++)
#pragma unroll
        for (int j = 0; j < 4; j++)
#pragma unroll
            for (int c = 0; c < 4; c++) acc[i][j][c] = 0.f;

    const int nk = K / BK;   // 32

    issue_stage(sbase + 0 * STAGE_B, Ahg, Alg, Bg, bm0, bn0, K, 0, tid);
    CP_COMMIT();
    issue_stage(sbase + 1 * STAGE_B, Ahg, Alg, Bg, bm0, bn0, K, BK, tid);
    CP_COMMIT();

    const uint32_t a_off = (uint32_t)(lane & 15) * (PITCH * 2) + (uint32_t)(lane >> 4) * 16;
    const uint32_t b_off = (uint32_t)(lane & 7) * (PITCH * 2) + (uint32_t)((lane >> 3) & 1) * 16;

    for (int it = 0; it < nk; it++) {
        CP_WAIT1();
        __syncthreads();
        const uint32_t st = sbase + (it & 1) * STAGE_B;
#pragma unroll
        for (int ks = 0; ks < 2; ks++) {
            uint32_t ah[4][4], al[4][4];
#pragma unroll
            for (int i = 0; i < 4; i++) {
                const uint32_t ro = st + (uint32_t)(wm + i * 16) * (PITCH * 2)
                                  + (uint32_t)(ks * 32) + a_off;
                ldmatrix_x4(ah[i], ro);
                ldmatrix_x4(al[i], ro + TILE_B);
            }
#pragma unroll
            for (int j = 0; j < 4; j++) {
                uint32_t b2[2];
                const uint32_t ro = st + 2 * TILE_B + (uint32_t)(wn + j * 8) * (PITCH * 2)
                                  + (uint32_t)(ks * 32) + b_off;
                ldmatrix_x2(b2, ro);
#pragma unroll
                for (int i = 0; i < 4; i++) {
                    mma_f16(acc[i][j], ah[i], b2);
                    mma_f16(acc[i][j], al[i], b2);
                }
            }
        }
        __syncthreads();
        if (it + 2 < nk)
            issue_stage(st, Ahg, Alg, Bg, bm0, bn0, K, (it + 2) * BK, tid);
        CP_COMMIT();
    }

    const int lr = lane >> 2;
    const int lc = (lane & 3) * 2;
#pragma unroll
    for (int i = 0; i < 4; i++) {
#pragma unroll
        for (int j = 0; j < 4; j++) {
            const int col = bn0 + wn + j * 8 + lc;
            const float bx = bias[col], by = bias[col + 1];
#pragma unroll
            for (int h2 = 0; h2 < 2; h2++) {
                const int row = bm0 + wm + i * 16 + lr + h2 * 8;
                float vx = acc[i][j][h2 * 2 + 0] + bx;
                float vy = acc[i][j][h2 * 2 + 1] + by;
                if (mode == 0) {
                    float2 v = make_float2(vx, vy);
                    *(float2*)&C[(size_t)row * N + col] = v;
                } else {
                    const int sec = col >> 10;
                    if (sec == 1) { vx *= QSCALE; vy *= QSCALE; }
                    const int hh  = (col >> 6) & 15;
                    const int d   = col & 63;
                    const int b_  = row >> 11;
                    const int s   = row & 2047;
                    const size_t off = (((size_t)(b_ * NH + hh)) * S_LEN + s) * HD + d;
                    __nv_bfloat16 hx = __float2bfloat16(vx);
                    __nv_bfloat16 hy = __float2bfloat16(vy);
                    __nv_bfloat16 lx = __float2bfloat16(vx - __bfloat162float(hx));
                    __nv_bfloat16 ly = __float2bfloat16(vy - __bfloat162float(hy));
                    __nv_bfloat16* dh = (sec == 0) ? kh : ((sec == 1) ? qh : vh);
                    __nv_bfloat16* dl = (sec == 0) ? kl : ((sec == 1) ? ql : vl);
                    __nv_bfloat162 hv; hv.x = hx; hv.y = hy;
                    __nv_bfloat162 lv; lv.x = lx; lv.y = ly;
                    *(__nv_bfloat162*)&dh[off] = hv;
                    *(__nv_bfloat162*)&dl[off] = lv;
                }
            }
        }
    }
}

// ---------------------------------------------------------------------------
// Flash attention (causal) on mma.sync, bf16x3 precision — R7 version
// (3-stage KV pipeline, one sync per tile, unpaired issue order).
// Output written as fp16 hi/lo into the proj GEMM input buffers.
// ---------------------------------------------------------------------------
#define KPITCH 144                       // bytes per 64-dim row (72 bf16)
#define QT (128 * KPITCH)                // 18432 B per Q component
#define CT (64 * KPITCH)                 // 9216 B per KV component tile
#define KVNST 3
#define ATT_SMEM (2 * QT + KVNST * 4 * CT)   // 147456 B

static __device__ __forceinline__ void issue_kv(
    uint32_t dst, const __nv_bfloat16* __restrict__ Kh, const __nv_bfloat16* __restrict__ Kl,
    const __nv_bfloat16* __restrict__ Vh, const __nv_bfloat16* __restrict__ Vl,
    size_t gbase, int k0, int tid)
{
    const int r = tid >> 2;
    const int c = tid & 3;
    const size_t g = gbase + (size_t)(k0 + r) * HD;
#pragma unroll
    for (int cc = 0; cc < 2; cc++) {
        const int ch = c + cc * 4;
        const uint32_t so = (uint32_t)(r * KPITCH + ch * 16);
        cp_async16(dst + 0 * CT + so, Kh + g + ch * 8);
        cp_async16(dst + 1 * CT + so, Kl + g + ch * 8);
        cp_async16(dst + 2 * CT + so, Vh + g + ch * 8);
        cp_async16(dst + 3 * CT + so, Vl + g + ch * 8);
    }
}

__global__ __launch_bounds__(256)
void attn_mma_kernel(
    const __nv_bfloat16* __restrict__ Qh, const __nv_bfloat16* __restrict__ Ql,
    const __nv_bfloat16* __restrict__ Kh, const __nv_bfloat16* __restrict__ Kl,
    const __nv_bfloat16* __restrict__ Vh, const __nv_bfloat16* __restrict__ Vl,
    __half* __restrict__ Oh, __half* __restrict__ Ol)
{
    extern __shared__ char smem[];
    const uint32_t sb = smem_u32(smem);
    const uint32_t sQ = sb;                  // Qh tile, Ql at +QT
    const uint32_t sKV = sb + 2 * QT;        // KVNST stages of 4*CT

    const int tid = threadIdx.x;
    const int lane = tid & 31;
    const int w = tid >> 5;
    const int qb = (int)gridDim.x - 1 - (int)blockIdx.x;   // long blocks first
    const int bh = blockIdx.y;
    const int q0 = qb * 128;
    const size_t base = (size_t)bh * S_LEN * HD;

    // load Q hi/lo tile (group 0)
    {
        const int r = tid >> 1;
        const int c0 = (tid & 1) * 4;
#pragma unroll
        for (int c = c0; c < c0 + 4; c++) {
            const uint32_t so = (uint32_t)(r * KPITCH + c * 16);
            const size_t g = base + (size_t)(q0 + r) * HD + c * 8;
            cp_async16(sQ + so, Qh + g);
            cp_async16(sQ + QT + so, Ql + g);
        }
    }
    CP_COMMIT();

    const int nt = 2 * qb + 2;
    issue_kv(sKV + 0 * 4 * CT, Kh, Kl, Vh, Vl, base, 0, tid);
    CP_COMMIT();
    if (nt > 1) {
        issue_kv(sKV + 1 * 4 * CT, Kh, Kl, Vh, Vl, base, 64, tid);
    }
    CP_COMMIT();

    CP_WAIT2();          // Q done (kv0, kv1 may be pending)
    __syncthreads();

    // resident Q fragments
    const int wm = w * 16;
    uint32_t qfh[4][4], qfl[4][4];
    {
        const uint32_t ab = sQ + (uint32_t)((wm + (lane & 15)) * KPITCH + (lane >> 4) * 16);
#pragma unroll
        for (int kk = 0; kk < 4; kk++) {
            ldmatrix_x4(qfh[kk], ab + kk * 32);
            ldmatrix_x4(qfl[kk], ab + QT + kk * 32);
        }
    }

    float o[8][4];
#pragma unroll
    for (int j = 0; j < 8; j++)
#pragma unroll
        for (int c = 0; c < 4; c++) o[j][c] = 0.f;
    float m0 = -1e30f, m1 = -1e30f, l0 = 0.f, l1 = 0.f;

    int stage = 0, wstage = 2 % KVNST;
    for (int it = 0; it < nt; it++) {
        CP_WAIT1();          // kv(it) done (<=1 pending: kv(it+1))
        __syncthreads();     // visible; all warps finished stage (it-1)
        if (it + 2 < nt) {
            issue_kv(sKV + wstage * 4 * CT, Kh, Kl, Vh, Vl, base, (it + 2) * 64, tid);
            CP_COMMIT();
        } else {
            CP_COMMIT();     // keep group counts uniform
        }

        const int k0 = it * 64;
        const bool active = (k0 <= q0 + wm + 15);
        if (active) {
            const uint32_t st = sKV + stage * 4 * CT;

            // ---- S = Q K^T (bf16x3), per warp m16 x n64 ----
            float s[8][4];
#pragma unroll
            for (int j = 0; j < 8; j++)
#pragma unroll
                for (int c = 0; c < 4; c++) s[j][c] = 0.f;

            const uint32_t kb_ = st + (uint32_t)((lane & 7) * KPITCH + ((lane >> 3) & 1) * 16);
#pragma unroll
            for (int kk = 0; kk < 4; kk++) {
#pragma unroll
                for (int j = 0; j < 8; j++) {
                    uint32_t bh2[2], bl2[2];
                    const uint32_t ro = kb_ + (uint32_t)(j * 8 * KPITCH + kk * 32);
                    ldmatrix_x2(bh2, ro);
                    ldmatrix_x2(bl2, ro + CT);
                    mma_bf16(s[j], qfh[kk], bh2);
                    mma_bf16(s[j], qfh[kk], bl2);
                    mma_bf16(s[j], qfl[kk], bh2);
                }
            }

            // ---- causal mask (log2 domain; Q pre-scaled) ----
            if (k0 + 63 > q0 + wm) {
#pragma unroll
                for (int j = 0; j < 8; j++)
#pragma unroll
                    for (int c = 0; c < 4; c++) {
                        const int kc = k0 + j * 8 + 2 * (lane & 3) + (c & 1);
                        const int rq = q0 + wm + (lane >> 2) + (c >> 1) * 8;
                        if (kc > rq) s[j][c] = -1e30f;
                    }
            }

            // ---- online softmax (exp2 domain) ----
            float mx0 = -1e30f, mx1 = -1e30f;
#pragma unroll
            for (int j = 0; j < 8; j++) {
                mx0 = fmaxf(mx0, fmaxf(s[j][0], s[j][1]));
                mx1 = fmaxf(mx1, fmaxf(s[j][2], s[j][3]));
            }
            mx0 = fmaxf(mx0, __shfl_xor_sync(0xffffffffu, mx0, 1));
            mx0 = fmaxf(mx0, __shfl_xor_sync(0xffffffffu, mx0, 2));
            mx1 = fmaxf(mx1, __shfl_xor_sync(0xffffffffu, mx1, 1));
            mx1 = fmaxf(mx1, __shfl_xor_sync(0xffffffffu, mx1, 2));

            const float mn0 = fmaxf(m0, mx0);
            const float mn1 = fmaxf(m1, mx1);
            const float f0 = ex2f(m0 - mn0);
            const float f1 = ex2f(m1 - mn1);
            m0 = mn0; m1 = mn1;

            float sum0 = 0.f, sum1 = 0.f;
#pragma unroll
            for (int j = 0; j < 8; j++) {
                s[j][0] = ex2f(s[j][0] - mn0);
                s[j][1] = ex2f(s[j][1] - mn0);
                s[j][2] = ex2f(s[j][2] - mn1);
                s[j][3] = ex2f(s[j][3] - mn1);
                sum0 += s[j][0] + s[j][1];
                sum1 += s[j][2] + s[j][3];
            }
            sum0 += __shfl_xor_sync(0xffffffffu, sum0, 1);
            sum0 += __shfl_xor_sync(0xffffffffu, sum0, 2);
            sum1 += __shfl_xor_sync(0xffffffffu, sum1, 1);
            sum1 += __shfl_xor_sync(0xffffffffu, sum1, 2);
            l0 = l0 * f0 + sum0;
            l1 = l1 * f1 + sum1;

#pragma unroll
            for (int j = 0; j < 8; j++) {
                o[j][0] *= f0; o[j][1] *= f0;
                o[j][2] *= f1; o[j][3] *= f1;
            }

            // ---- O += P V (bf16x3), P from fragments ----
            const uint32_t vb_ = st + 2 * CT + (uint32_t)((lane & 15) * KPITCH);
#pragma unroll
            for (int t = 0; t < 4; t++) {
                uint32_t ph[4], pl[4];
#pragma unroll
                for (int half = 0; half < 2; half++) {
                    const float* sp = s[2 * t + half];
                    __nv_bfloat162 h01 = __float22bfloat162_rn(make_float2(sp[0], sp[1]));
                    __nv_bfloat162 h23 = __float22bfloat162_rn(make_float2(sp[2], sp[3]));
                    __nv_bfloat162 r01 = __float22bfloat162_rn(make_float2(
                        sp[0] - __bfloat162float(h01.x), sp[1] - __bfloat162float(h01.y)));
                    __nv_bfloat162 r23 = __float22bfloat162_rn(make_float2(
                        sp[2] - __bfloat162float(h23.x), sp[3] - __bfloat162float(h23.y)));
                    ph[2 * half + 0] = *(uint32_t*)&h01;
                    ph[2 * half + 1] = *(uint32_t*)&h23;
                    pl[2 * half + 0] = *(uint32_t*)&r01;
                    pl[2 * half + 1] = *(uint32_t*)&r23;
                }
                uint32_t pa_h[4] = {ph[0], ph[1], ph[2], ph[3]};
                uint32_t pa_l[4] = {pl[0], pl[1], pl[2], pl[3]};
#pragma unroll
                for (int jd = 0; jd < 8; jd++) {
                    uint32_t vh2[2], vl2[2];
                    const uint32_t vo = vb_ + (uint32_t)(16 * t * KPITCH + jd * 16);
                    ldmatrix_x2_trans(vh2, vo);
                    ldmatrix_x2_trans(vl2, vo + CT);
                    mma_bf16(o[jd], pa_h, vh2);
                    mma_bf16(o[jd], pa_h, vl2);
                    mma_bf16(o[jd], pa_l, vh2);
                }
            }
        }

        if (++stage == KVNST) stage = 0;
        if (++wstage == KVNST) wstage = 0;
    }

    // ---- epilogue: normalize, split fp16 hi/lo, write [M,E] ----
    const int b = bh >> 4;
    const int h = bh & 15;
    const float inv0 = 1.0f / l0;
    const float inv1 = 1.0f / l1;
    const int r0 = b * S_LEN + q0 + wm + (lane >> 2);
    const int colb = h * HD + 2 * (lane & 3);
#pragma unroll
    for (int jd = 0; jd < 8; jd++) {
        const int col = colb + jd * 8;
#pragma unroll
        for (int h2 = 0; h2 < 2; h2++) {
            const float inv = h2 ? inv1 : inv0;
            const float vx = o[jd][h2 * 2 + 0] * inv;
            const float vy = o[jd][h2 * 2 + 1] * inv;
            const size_t off = (size_t)(r0 + h2 * 8) * EMB + col;
            __half2 hv = __floats2half2_rn(vx, vy);
            __half2 lv = __floats2half2_rn(vx - __half2float(__low2half(hv)),
                                           vy - __half2float(__high2half(hv)));
            *(__half2*)&Oh[off] = hv;
            *(__half2*)&Ol[off] = lv;
        }
    }
}

// ---------------------------------------------------------------------------
// Launch
// ---------------------------------------------------------------------------
extern "C" void kernel_launch(void* const* d_in, const int* in_sizes, int n_in,
                              void* d_out, int out_size)
{
    const float* x      = (const float*)d_in[0];
    const float* W_qkv  = (const float*)d_in[1];
    const float* b_qkv  = (const float*)d_in[2];
    const float* W_proj = (const float*)d_in[3];
    const float* b_proj = (const float*)d_in[4];
    float* out = (float*)d_out;

    __half *Ah, *Al, *WQ, *WP;
    __nv_bfloat16 *Qh, *Ql, *Kh, *Kl, *Vh, *Vl;
    cudaGetSymbolAddress((void**)&Ah, g_Ah);
    cudaGetSymbolAddress((void**)&Al, g_Al);
    cudaGetSymbolAddress((void**)&WQ, g_WQ);
    cudaGetSymbolAddress((void**)&WP, g_WP);
    cudaGetSymbolAddress((void**)&Qh, g_Qh);
    cudaGetSymbolAddress((void**)&Ql, g_Ql);
    cudaGetSymbolAddress((void**)&Kh, g_Kh);
    cudaGetSymbolAddress((void**)&Kl, g_Kl);
    cudaGetSymbolAddress((void**)&Vh, g_Vh);
    cudaGetSymbolAddress((void**)&Vl, g_Vl);

    cudaFuncSetAttribute(gemm_f16x2_kernel,
                         cudaFuncAttributeMaxDynamicSharedMemorySize, GEMM_SMEM);
    cudaFuncSetAttribute(attn_mma_kernel,
                         cudaFuncAttributeMaxDynamicSharedMemorySize, ATT_SMEM);

    // 0) pre-convert weights (transposed, fp16) and input activations (fp16 hi/lo)
    {
        dim3 blk(32, 8);
        conv_wT_kernel<<<dim3(3 * EMB / 32, EMB / 32), blk>>>(W_qkv, WQ, EMB, 3 * EMB);
        conv_wT_kernel<<<dim3(EMB / 32, EMB / 32), blk>>>(W_proj, WP, EMB, EMB);
        const int n4 = MTOT * EMB / 4;
        conv_act_kernel<<<n4 / 256, 256>>>((const float4*)x, (__half2*)Ah, (__half2*)Al, n4);
    }

    // 1) QKV projection (fp16x2) -> hi/lo bf16 K/Q/V in [B,H,S,D] (Q pre-scaled)
    gemm_f16x2_kernel<<<dim3(3 * EMB / 128, MTOT / 128), 256, GEMM_SMEM>>>(
        Ah, Al, WQ, b_qkv, nullptr, MTOT, 3 * EMB, EMB, 1,
        Kh, Kl, Qh, Ql, Vh, Vl);

    // 2) fused causal flash attention (bf16x3) -> fp16 hi/lo Ah/Al
    attn_mma_kernel<<<dim3(S_LEN / 128, BATCH * NH), 256, ATT_SMEM>>>(
        Qh, Ql, Kh, Kl, Vh, Vl, Ah, Al);

    // 3) output projection (fp16x2) -> fp32 out
    gemm_f16x2_kernel<<<dim3(EMB / 128, MTOT / 128), 256, GEMM_SMEM>>>(
        Ah, Al, WP, b_proj, out, MTOT, EMB, EMB, 0,
        nullptr, nullptr, nullptr, nullptr, nullptr, nullptr);
}

// round 10
// speedup vs baseline: 1.4519x; 1.2039x over previous
#include <cuda_runtime.h>
#include <cuda_bf16.h>
#include <cuda_fp16.h>
#include <cstdint>

#define BATCH 4
#define S_LEN 2048
#define EMB   1024
#define NH    16
#define HD    64
#define MTOT  (BATCH * S_LEN)   // 8192

// ---------------------------------------------------------------------------
// Device-global scratch (allocation-free requirement)
// ---------------------------------------------------------------------------
static __device__ __half g_Ah[MTOT * EMB];               // GEMM A hi (fp16)
static __device__ __half g_Al[MTOT * EMB];               // GEMM A lo (fp16)
static __device__ __half g_WQ[3 * EMB * EMB];            // W_qkv^T fp16 [N=3072,K=1024]
static __device__ __half g_WP[EMB * EMB];                // W_proj^T fp16 [N=1024,K=1024]

static __device__ __half g_Qh[BATCH * NH * S_LEN * HD];  // Q hi (pre-scaled, fp16)
static __device__ __half g_Ql[BATCH * NH * S_LEN * HD];  // Q lo
static __device__ __half g_K [BATCH * NH * S_LEN * HD];  // K single fp16
static __device__ __half g_V [BATCH * NH * S_LEN * HD];  // V single fp16

// ---------------------------------------------------------------------------
// Portable PTX helpers (compute_100-safe)
// ---------------------------------------------------------------------------
static __device__ __forceinline__ uint32_t smem_u32(const void* p) {
    uint32_t a;
    asm("{ .reg .u64 t; cvta.to.shared.u64 t, %1; cvt.u32.u64 %0, t; }" : "=r"(a) : "l"(p));
    return a;
}
static __device__ __forceinline__ void cp_async16(uint32_t dst, const void* src) {
    asm volatile("cp.async.cg.shared.global [%0], [%1], 16;" :: "r"(dst), "l"(src) : "memory");
}
#define CP_COMMIT() asm volatile("cp.async.commit_group;" ::: "memory")
#define CP_WAIT1()  asm volatile("cp.async.wait_group 1;" ::: "memory")
#define CP_WAIT2()  asm volatile("cp.async.wait_group 2;" ::: "memory")

static __device__ __forceinline__ void ldmatrix_x4(uint32_t* r, uint32_t addr) {
    asm volatile("ldmatrix.sync.aligned.m8n8.x4.shared.b16 {%0,%1,%2,%3}, [%4];"
                 : "=r"(r[0]), "=r"(r[1]), "=r"(r[2]), "=r"(r[3]) : "r"(addr));
}
static __device__ __forceinline__ void ldmatrix_x2(uint32_t* r, uint32_t addr) {
    asm volatile("ldmatrix.sync.aligned.m8n8.x2.shared.b16 {%0,%1}, [%2];"
                 : "=r"(r[0]), "=r"(r[1]) : "r"(addr));
}
static __device__ __forceinline__ void ldmatrix_x2_trans(uint32_t* r, uint32_t addr) {
    asm volatile("ldmatrix.sync.aligned.m8n8.x2.trans.shared.b16 {%0,%1}, [%2];"
                 : "=r"(r[0]), "=r"(r[1]) : "r"(addr));
}
static __device__ __forceinline__ void mma_f16(float* d, const uint32_t* a, const uint32_t* b) {
    asm volatile("mma.sync.aligned.m16n8k16.row.col.f32.f16.f16.f32 "
                 "{%0,%1,%2,%3}, {%4,%5,%6,%7}, {%8,%9}, {%0,%1,%2,%3};"
                 : "+f"(d[0]), "+f"(d[1]), "+f"(d[2]), "+f"(d[3])
                 : "r"(a[0]), "r"(a[1]), "r"(a[2]), "r"(a[3]), "r"(b[0]), "r"(b[1]));
}
static __device__ __forceinline__ float ex2f(float x) {
    float y;
    asm("ex2.approx.ftz.f32 %0, %1;" : "=f"(y) : "f"(x));
    return y;
}

// ---------------------------------------------------------------------------
// Pre-processing kernels (fp16 GEMM operands)
// ---------------------------------------------------------------------------
__global__ void conv_act_kernel(const float4* __restrict__ in,
                                __half2* __restrict__ hi, __half2* __restrict__ lo, int n4)
{
    int i = blockIdx.x * 256 + threadIdx.x;
    if (i >= n4) return;
    float4 v = in[i];
    __half2 h0 = __floats2half2_rn(v.x, v.y);
    __half2 h1 = __floats2half2_rn(v.z, v.w);
    __half2 l0 = __floats2half2_rn(v.x - __half2float(__low2half(h0)),
                                   v.y - __half2float(__high2half(h0)));
    __half2 l1 = __floats2half2_rn(v.z - __half2float(__low2half(h1)),
                                   v.w - __half2float(__high2half(h1)));
    hi[i * 2 + 0] = h0;
    hi[i * 2 + 1] = h1;
    lo[i * 2 + 0] = l0;
    lo[i * 2 + 1] = l1;
}

// W [K,N] fp32 -> W^T [N,K] fp16 (tiled transpose)
__global__ void conv_wT_kernel(const float* __restrict__ W,
                               __half* __restrict__ Th, int Kd, int Nd)
{
    __shared__ float t[32][33];
    const int n0 = blockIdx.x * 32, k0 = blockIdx.y * 32;
    const int tx = threadIdx.x, ty = threadIdx.y;
#pragma unroll
    for (int j = 0; j < 32; j += 8)
        t[ty + j][tx] = W[(size_t)(k0 + ty + j) * Nd + n0 + tx];
    __syncthreads();
#pragma unroll
    for (int j = 0; j < 32; j += 8) {
        float v = t[tx][ty + j];
        Th[(size_t)(n0 + ty + j) * Kd + k0 + tx] = __float2half_rn(v);
    }
}

// ---------------------------------------------------------------------------
// fp16 2-product mma.sync GEMM — R4 skeleton: 128x128 tile, 8 warps (64x32),
// BK=32, pitch-40 smem, 2-stage cp.async pipeline, 2 CTAs/SM.
// mode 0: fp32 C (+bias). mode 1: QKV epilogue -> Q hi/lo fp16 (pre-scaled),
// K/V single fp16, all in [B,H,S,D].
// ---------------------------------------------------------------------------
#define BK      32
#define PITCH   40                       // fp16 units (80 B rows, conflict-free)
#define TILE_B  (128 * PITCH * 2)        // 10240 B
#define STAGE_B (3 * TILE_B)             // 30720 B (Ah, Al, W)
#define GEMM_SMEM (2 * STAGE_B)          // 61440 B

#define QSCALE  0.1803368801111244f      // 0.125 * log2(e)

static __device__ __forceinline__ void issue_stage(
    uint32_t sstage, const __half* __restrict__ Ahg,
    const __half* __restrict__ Alg, const __half* __restrict__ Bg,
    int bm0, int bn0, int K, int kof, int tid)
{
    const int r = tid >> 1;               // 0..127
    const int c0 = (tid & 1) * 2;         // chunk pair
#pragma unroll
    for (int cc = 0; cc < 2; cc++) {
        const int c = c0 + cc;
        const uint32_t so = (uint32_t)(r * (PITCH * 2) + c * 16);
        const size_t ga = (size_t)(bm0 + r) * K + kof + c * 8;
        const size_t gb = (size_t)(bn0 + r) * K + kof + c * 8;
        cp_async16(sstage + 0 * TILE_B + so, Ahg + ga);
        cp_async16(sstage + 1 * TILE_B + so, Alg + ga);
        cp_async16(sstage + 2 * TILE_B + so, Bg + gb);
    }
}

__global__ __launch_bounds__(256, 2)
void gemm_f16x2_kernel(
    const __half* __restrict__ Ahg, const __half* __restrict__ Alg,
    const __half* __restrict__ Bg,
    const float* __restrict__ bias, float* __restrict__ C,
    int M, int N, int K, int mode,
    __half* __restrict__ kg, __half* __restrict__ qh,
    __half* __restrict__ ql, __half* __restrict__ vg)
{
    extern __shared__ char smem[];
    const uint32_t sbase = smem_u32(smem);
    const int tid  = threadIdx.x;
    const int wid  = tid >> 5;
    const int lane = tid & 31;
    const int bm0 = blockIdx.y * 128;
    const int bn0 = blockIdx.x * 128;

    const int wm = (wid & 1) * 64;
    const int wn = (wid >> 1) * 32;

    float acc[4][4][4];
#pragma unroll
    for (int i = 0; i < 4; i++)
#pragma unroll
        for (int j = 0; j < 4; j++)
#pragma unroll
            for (int c = 0; c < 4; c++) acc[i][j][c] = 0.f;

    const int nk = K / BK;   // 32

    issue_stage(sbase + 0 * STAGE_B, Ahg, Alg, Bg, bm0, bn0, K, 0, tid);
    CP_COMMIT();
    issue_stage(sbase + 1 * STAGE_B, Ahg, Alg, Bg, bm0, bn0, K, BK, tid);
    CP_COMMIT();

    const uint32_t a_off = (uint32_t)(lane & 15) * (PITCH * 2) + (uint32_t)(lane >> 4) * 16;
    const uint32_t b_off = (uint32_t)(lane & 7) * (PITCH * 2) + (uint32_t)((lane >> 3) & 1) * 16;

    for (int it = 0; it < nk; it++) {
        CP_WAIT1();
        __syncthreads();
        const uint32_t st = sbase + (it & 1) * STAGE_B;
#pragma unroll
        for (int ks = 0; ks < 2; ks++) {
            uint32_t ah[4][4], al[4][4];
#pragma unroll
            for (int i = 0; i < 4; i++) {
                const uint32_t ro = st + (uint32_t)(wm + i * 16) * (PITCH * 2)
                                  + (uint32_t)(ks * 32) + a_off;
                ldmatrix_x4(ah[i], ro);
                ldmatrix_x4(al[i], ro + TILE_B);
            }
#pragma unroll
            for (int j = 0; j < 4; j++) {
                uint32_t b2[2];
                const uint32_t ro = st + 2 * TILE_B + (uint32_t)(wn + j * 8) * (PITCH * 2)
                                  + (uint32_t)(ks * 32) + b_off;
                ldmatrix_x2(b2, ro);
#pragma unroll
                for (int i = 0; i < 4; i++) {
                    mma_f16(acc[i][j], ah[i], b2);
                    mma_f16(acc[i][j], al[i], b2);
                }
            }
        }
        __syncthreads();
        if (it + 2 < nk)
            issue_stage(st, Ahg, Alg, Bg, bm0, bn0, K, (it + 2) * BK, tid);
        CP_COMMIT();
    }

    const int lr = lane >> 2;
    const int lc = (lane & 3) * 2;
#pragma unroll
    for (int i = 0; i < 4; i++) {
#pragma unroll
        for (int j = 0; j < 4; j++) {
            const int col = bn0 + wn + j * 8 + lc;
            const float bx = bias[col], by = bias[col + 1];
#pragma unroll
            for (int h2 = 0; h2 < 2; h2++) {
                const int row = bm0 + wm + i * 16 + lr + h2 * 8;
                float vx = acc[i][j][h2 * 2 + 0] + bx;
                float vy = acc[i][j][h2 * 2 + 1] + by;
                if (mode == 0) {
                    float2 v = make_float2(vx, vy);
                    *(float2*)&C[(size_t)row * N + col] = v;
                } else {
                    const int sec = col >> 10;
                    const int hh  = (col >> 6) & 15;
                    const int d   = col & 63;
                    const int b_  = row >> 11;
                    const int s   = row & 2047;
                    const size_t off = (((size_t)(b_ * NH + hh)) * S_LEN + s) * HD + d;
                    if (sec == 1) {
                        vx *= QSCALE; vy *= QSCALE;
                        __half2 hv = __floats2half2_rn(vx, vy);
                        __half2 lv = __floats2half2_rn(
                            vx - __half2float(__low2half(hv)),
                            vy - __half2float(__high2half(hv)));
                        *(__half2*)&qh[off] = hv;
                        *(__half2*)&ql[off] = lv;
                    } else {
                        __half2 hv = __floats2half2_rn(vx, vy);
                        *(__half2*)&((sec == 0) ? kg : vg)[off] = hv;
                    }
                }
            }
        }
    }
}

// ---------------------------------------------------------------------------
// Flash attention (causal), fp16 2-product scheme.
// Block: 128 q-rows x (B*H). 8 warps, each warp m16 x n64.
// Q exact fp16 hi/lo (resident fragments); K, V single fp16.
// 64-key KV tiles (K+V = 18432 B/stage), 3-stage cp.async pipeline,
// one sync per tile. 2 CTAs/SM (92 KB smem).
// Output written as fp16 hi/lo into the proj GEMM input buffers.
// ---------------------------------------------------------------------------
#define KPITCH 144                       // bytes per 64-dim fp16 row (72 fp16)
#define QT (128 * KPITCH)                // 18432 B per Q component
#define CT (64 * KPITCH)                 // 9216 B per K or V tile
#define KVNST 3
#define ATT_SMEM (2 * QT + KVNST * 2 * CT)   // 92160 B

static __device__ __forceinline__ void issue_kv(
    uint32_t dst, const __half* __restrict__ Kg, const __half* __restrict__ Vg,
    size_t gbase, int k0, int tid)
{
    const int r = tid >> 2;
    const int c = tid & 3;
    const size_t g = gbase + (size_t)(k0 + r) * HD;
#pragma unroll
    for (int cc = 0; cc < 2; cc++) {
        const int ch = c + cc * 4;
        const uint32_t so = (uint32_t)(r * KPITCH + ch * 16);
        cp_async16(dst + 0 * CT + so, Kg + g + ch * 8);
        cp_async16(dst + 1 * CT + so, Vg + g + ch * 8);
    }
}

__global__ __launch_bounds__(256, 2)
void attn_mma_kernel(
    const __half* __restrict__ Qh, const __half* __restrict__ Ql,
    const __half* __restrict__ Kg, const __half* __restrict__ Vg,
    __half* __restrict__ Oh, __half* __restrict__ Ol)
{
    extern __shared__ char smem[];
    const uint32_t sb = smem_u32(smem);
    const uint32_t sQ = sb;                  // Qh tile, Ql at +QT
    const uint32_t sKV = sb + 2 * QT;        // KVNST stages of 2*CT

    const int tid = threadIdx.x;
    const int lane = tid & 31;
    const int w = tid >> 5;
    const int qb = (int)gridDim.x - 1 - (int)blockIdx.x;   // long blocks first
    const int bh = blockIdx.y;
    const int q0 = qb * 128;
    const size_t base = (size_t)bh * S_LEN * HD;

    // load Q hi/lo tile (group 0)
    {
        const int r = tid >> 1;
        const int c0 = (tid & 1) * 4;
#pragma unroll
        for (int c = c0; c < c0 + 4; c++) {
            const uint32_t so = (uint32_t)(r * KPITCH + c * 16);
            const size_t g = base + (size_t)(q0 + r) * HD + c * 8;
            cp_async16(sQ + so, Qh + g);
            cp_async16(sQ + QT + so, Ql + g);
        }
    }
    CP_COMMIT();

    const int nt = 2 * qb + 2;
    issue_kv(sKV + 0 * 2 * CT, Kg, Vg, base, 0, tid);
    CP_COMMIT();
    if (nt > 1) {
        issue_kv(sKV + 1 * 2 * CT, Kg, Vg, base, 64, tid);
    }
    CP_COMMIT();

    CP_WAIT2();          // Q done (kv0, kv1 may be pending)
    __syncthreads();

    // resident Q fragments (fp16 hi/lo)
    const int wm = w * 16;
    uint32_t qfh[4][4], qfl[4][4];
    {
        const uint32_t ab = sQ + (uint32_t)((wm + (lane & 15)) * KPITCH + (lane >> 4) * 16);
#pragma unroll
        for (int kk = 0; kk < 4; kk++) {
            ldmatrix_x4(qfh[kk], ab + kk * 32);
            ldmatrix_x4(qfl[kk], ab + QT + kk * 32);
        }
    }

    float o[8][4];
#pragma unroll
    for (int j = 0; j < 8; j++)
#pragma unroll
        for (int c = 0; c < 4; c++) o[j][c] = 0.f;
    float m0 = -1e30f, m1 = -1e30f, l0 = 0.f, l1 = 0.f;

    int stage = 0, wstage = 2 % KVNST;
    for (int it = 0; it < nt; it++) {
        CP_WAIT1();          // kv(it) done (<=1 pending: kv(it+1))
        __syncthreads();     // visible; all warps finished stage (it-1)
        if (it + 2 < nt) {
            issue_kv(sKV + wstage * 2 * CT, Kg, Vg, base, (it + 2) * 64, tid);
            CP_COMMIT();
        } else {
            CP_COMMIT();     // keep group counts uniform
        }

        const int k0 = it * 64;
        const bool active = (k0 <= q0 + wm + 15);
        if (active) {
            const uint32_t st = sKV + stage * 2 * CT;

            // ---- S = Q K^T (fp16x2), per warp m16 x n64 ----
            float s[8][4];
#pragma unroll
            for (int j = 0; j < 8; j++)
#pragma unroll
                for (int c = 0; c < 4; c++) s[j][c] = 0.f;

            const uint32_t kb_ = st + (uint32_t)((lane & 7) * KPITCH + ((lane >> 3) & 1) * 16);
#pragma unroll
            for (int kk = 0; kk < 4; kk++) {
#pragma unroll
                for (int j = 0; j < 8; j++) {
                    uint32_t k2[2];
                    const uint32_t ro = kb_ + (uint32_t)(j * 8 * KPITCH + kk * 32);
                    ldmatrix_x2(k2, ro);
                    mma_f16(s[j], qfh[kk], k2);
                    mma_f16(s[j], qfl[kk], k2);
                }
            }

            // ---- causal mask (log2 domain; Q pre-scaled) ----
            if (k0 + 63 > q0 + wm) {
#pragma unroll
                for (int j = 0; j < 8; j++)
#pragma unroll
                    for (int c = 0; c < 4; c++) {
                        const int kc = k0 + j * 8 + 2 * (lane & 3) + (c & 1);
                        const int rq = q0 + wm + (lane >> 2) + (c >> 1) * 8;
                        if (kc > rq) s[j][c] = -1e30f;
                    }
            }

            // ---- online softmax (exp2 domain) ----
            float mx0 = -1e30f, mx1 = -1e30f;
#pragma unroll
            for (int j = 0; j < 8; j++) {
                mx0 = fmaxf(mx0, fmaxf(s[j][0], s[j][1]));
                mx1 = fmaxf(mx1, fmaxf(s[j][2], s[j][3]));
            }
            mx0 = fmaxf(mx0, __shfl_xor_sync(0xffffffffu, mx0, 1));
            mx0 = fmaxf(mx0, __shfl_xor_sync(0xffffffffu, mx0, 2));
            mx1 = fmaxf(mx1, __shfl_xor_sync(0xffffffffu, mx1, 1));
            mx1 = fmaxf(mx1, __shfl_xor_sync(0xffffffffu, mx1, 2));

            const float mn0 = fmaxf(m0, mx0);
            const float mn1 = fmaxf(m1, mx1);
            const float f0 = ex2f(m0 - mn0);
            const float f1 = ex2f(m1 - mn1);
            m0 = mn0; m1 = mn1;

            float sum0 = 0.f, sum1 = 0.f;
#pragma unroll
            for (int j = 0; j < 8; j++) {
                s[j][0] = ex2f(s[j][0] - mn0);
                s[j][1] = ex2f(s[j][1] - mn0);
                s[j][2] = ex2f(s[j][2] - mn1);
                s[j][3] = ex2f(s[j][3] - mn1);
                sum0 += s[j][0] + s[j][1];
                sum1 += s[j][2] + s[j][3];
            }
            sum0 += __shfl_xor_sync(0xffffffffu, sum0, 1);
            sum0 += __shfl_xor_sync(0xffffffffu, sum0, 2);
            sum1 += __shfl_xor_sync(0xffffffffu, sum1, 1);
            sum1 += __shfl_xor_sync(0xffffffffu, sum1, 2);
            l0 = l0 * f0 + sum0;
            l1 = l1 * f1 + sum1;

#pragma unroll
            for (int j = 0; j < 8; j++) {
                o[j][0] *= f0; o[j][1] *= f0;
                o[j][2] *= f1; o[j][3] *= f1;
            }

            // ---- O += P V (fp16x2): P exact fp16 hi/lo, V single ----
            const uint32_t vb_ = st + CT + (uint32_t)((lane & 15) * KPITCH);
#pragma unroll
            for (int t = 0; t < 4; t++) {
                uint32_t ph[4], pl[4];
#pragma unroll
                for (int half = 0; half < 2; half++) {
                    const float* sp = s[2 * t + half];
                    __half2 h01 = __floats2half2_rn(sp[0], sp[1]);
                    __half2 h23 = __floats2half2_rn(sp[2], sp[3]);
                    __half2 r01 = __floats2half2_rn(
                        sp[0] - __half2float(__low2half(h01)),
                        sp[1] - __half2float(__high2half(h01)));
                    __half2 r23 = __floats2half2_rn(
                        sp[2] - __half2float(__low2half(h23)),
                        sp[3] - __half2float(__high2half(h23)));
                    ph[2 * half + 0] = *(uint32_t*)&h01;
                    ph[2 * half + 1] = *(uint32_t*)&h23;
                    pl[2 * half + 0] = *(uint32_t*)&r01;
                    pl[2 * half + 1] = *(uint32_t*)&r23;
                }
#pragma unroll
                for (int jd = 0; jd < 8; jd++) {
                    uint32_t v2[2];
                    const uint32_t vo = vb_ + (uint32_t)(16 * t * KPITCH + jd * 16);
                    ldmatrix_x2_trans(v2, vo);
                    mma_f16(o[jd], ph, v2);
                    mma_f16(o[jd], pl, v2);
                }
            }
        }

        if (++stage == KVNST) stage = 0;
        if (++wstage == KVNST) wstage = 0;
    }

    // ---- epilogue: normalize, split fp16 hi/lo, write [M,E] ----
    const int b = bh >> 4;
    const int h = bh & 15;
    const float inv0 = 1.0f / l0;
    const float inv1 = 1.0f / l1;
    const int r0 = b * S_LEN + q0 + wm + (lane >> 2);
    const int colb = h * HD + 2 * (lane & 3);
#pragma unroll
    for (int jd = 0; jd < 8; jd++) {
        const int col = colb + jd * 8;
#pragma unroll
        for (int h2 = 0; h2 < 2; h2++) {
            const float inv = h2 ? inv1 : inv0;
            const float vx = o[jd][h2 * 2 + 0] * inv;
            const float vy = o[jd][h2 * 2 + 1] * inv;
            const size_t off = (size_t)(r0 + h2 * 8) * EMB + col;
            __half2 hv = __floats2half2_rn(vx, vy);
            __half2 lv = __floats2half2_rn(vx - __half2float(__low2half(hv)),
                                           vy - __half2float(__high2half(hv)));
            *(__half2*)&Oh[off] = hv;
            *(__half2*)&Ol[off] = lv;
        }
    }
}

// ---------------------------------------------------------------------------
// Launch
// ---------------------------------------------------------------------------
extern "C" void kernel_launch(void* const* d_in, const int* in_sizes, int n_in,
                              void* d_out, int out_size)
{
    const float* x      = (const float*)d_in[0];
    const float* W_qkv  = (const float*)d_in[1];
    const float* b_qkv  = (const float*)d_in[2];
    const float* W_proj = (const float*)d_in[3];
    const float* b_proj = (const float*)d_in[4];
    float* out = (float*)d_out;

    __half *Ah, *Al, *WQ, *WP, *Qh, *Ql, *Kg, *Vg;
    cudaGetSymbolAddress((void**)&Ah, g_Ah);
    cudaGetSymbolAddress((void**)&Al, g_Al);
    cudaGetSymbolAddress((void**)&WQ, g_WQ);
    cudaGetSymbolAddress((void**)&WP, g_WP);
    cudaGetSymbolAddress((void**)&Qh, g_Qh);
    cudaGetSymbolAddress((void**)&Ql, g_Ql);
    cudaGetSymbolAddress((void**)&Kg, g_K);
    cudaGetSymbolAddress((void**)&Vg, g_V);

    cudaFuncSetAttribute(gemm_f16x2_kernel,
                         cudaFuncAttributeMaxDynamicSharedMemorySize, GEMM_SMEM);
    cudaFuncSetAttribute(attn_mma_kernel,
                         cudaFuncAttributeMaxDynamicSharedMemorySize, ATT_SMEM);

    // 0) pre-convert weights (transposed, fp16) and input activations (fp16 hi/lo)
    {
        dim3 blk(32, 8);
        conv_wT_kernel<<<dim3(3 * EMB / 32, EMB / 32), blk>>>(W_qkv, WQ, EMB, 3 * EMB);
        conv_wT_kernel<<<dim3(EMB / 32, EMB / 32), blk>>>(W_proj, WP, EMB, EMB);
        const int n4 = MTOT * EMB / 4;
        conv_act_kernel<<<n4 / 256, 256>>>((const float4*)x, (__half2*)Ah, (__half2*)Al, n4);
    }

    // 1) QKV projection (fp16x2) -> Q hi/lo fp16 (pre-scaled), K/V single fp16
    gemm_f16x2_kernel<<<dim3(3 * EMB / 128, MTOT / 128), 256, GEMM_SMEM>>>(
        Ah, Al, WQ, b_qkv, nullptr, MTOT, 3 * EMB, EMB, 1,
        Kg, Qh, Ql, Vg);

    // 2) fused causal flash attention (fp16x2) -> fp16 hi/lo Ah/Al
    attn_mma_kernel<<<dim3(S_LEN / 128, BATCH * NH), 256, ATT_SMEM>>>(
        Qh, Ql, Kg, Vg, Ah, Al);

    // 3) output projection (fp16x2) -> fp32 out
    gemm_f16x2_kernel<<<dim3(EMB / 128, MTOT / 128), 256, GEMM_SMEM>>>(
        Ah, Al, WP, b_proj, out, MTOT, EMB, EMB, 0,
        nullptr, nullptr, nullptr, nullptr);
}

// round 11
// speedup vs baseline: 1.5486x; 1.0666x over previous
#include <cuda_runtime.h>
#include <cuda_bf16.h>
#include <cuda_fp16.h>
#include <cstdint>

#define BATCH 4
#define S_LEN 2048
#define EMB   1024
#define NH    16
#define HD    64
#define MTOT  (BATCH * S_LEN)   // 8192

// ---------------------------------------------------------------------------
// Device-global scratch (allocation-free requirement)
// ---------------------------------------------------------------------------
static __device__ __half g_Ah[MTOT * EMB];               // GEMM A hi (fp16)
static __device__ __half g_Al[MTOT * EMB];               // GEMM A lo (fp16)
static __device__ __half g_WQ[3 * EMB * EMB];            // W_qkv^T fp16 [N=3072,K=1024]
static __device__ __half g_WP[EMB * EMB];                // W_proj^T fp16 [N=1024,K=1024]

static __device__ __half g_Qh[BATCH * NH * S_LEN * HD];  // Q hi (pre-scaled, fp16)
static __device__ __half g_Ql[BATCH * NH * S_LEN * HD];  // Q lo
static __device__ __half g_K [BATCH * NH * S_LEN * HD];  // K single fp16
static __device__ __half g_V [BATCH * NH * S_LEN * HD];  // V single fp16

// ---------------------------------------------------------------------------
// Portable PTX helpers (compute_100-safe)
// ---------------------------------------------------------------------------
static __device__ __forceinline__ uint32_t smem_u32(const void* p) {
    uint32_t a;
    asm("{ .reg .u64 t; cvta.to.shared.u64 t, %1; cvt.u32.u64 %0, t; }" : "=r"(a) : "l"(p));
    return a;
}
static __device__ __forceinline__ void cp_async16(uint32_t dst, const void* src) {
    asm volatile("cp.async.cg.shared.global [%0], [%1], 16;" :: "r"(dst), "l"(src) : "memory");
}
#define CP_COMMIT() asm volatile("cp.async.commit_group;" ::: "memory")
#define CP_WAIT1()  asm volatile("cp.async.wait_group 1;" ::: "memory")
#define CP_WAIT2()  asm volatile("cp.async.wait_group 2;" ::: "memory")

static __device__ __forceinline__ void ldmatrix_x4(uint32_t* r, uint32_t addr) {
    asm volatile("ldmatrix.sync.aligned.m8n8.x4.shared.b16 {%0,%1,%2,%3}, [%4];"
                 : "=r"(r[0]), "=r"(r[1]), "=r"(r[2]), "=r"(r[3]) : "r"(addr));
}
static __device__ __forceinline__ void ldmatrix_x4_trans(uint32_t* r, uint32_t addr) {
    asm volatile("ldmatrix.sync.aligned.m8n8.x4.trans.shared.b16 {%0,%1,%2,%3}, [%4];"
                 : "=r"(r[0]), "=r"(r[1]), "=r"(r[2]), "=r"(r[3]) : "r"(addr));
}
static __device__ __forceinline__ void mma_f16(float* d, const uint32_t* a, const uint32_t* b) {
    asm volatile("mma.sync.aligned.m16n8k16.row.col.f32.f16.f16.f32 "
                 "{%0,%1,%2,%3}, {%4,%5,%6,%7}, {%8,%9}, {%0,%1,%2,%3};"
                 : "+f"(d[0]), "+f"(d[1]), "+f"(d[2]), "+f"(d[3])
                 : "r"(a[0]), "r"(a[1]), "r"(a[2]), "r"(a[3]), "r"(b[0]), "r"(b[1]));
}
static __device__ __forceinline__ float ex2f(float x) {
    float y;
    asm("ex2.approx.ftz.f32 %0, %1;" : "=f"(y) : "f"(x));
    return y;
}

// ---------------------------------------------------------------------------
// Pre-processing kernels (fp16 GEMM operands)
// ---------------------------------------------------------------------------
__global__ void conv_act_kernel(const float4* __restrict__ in,
                                __half2* __restrict__ hi, __half2* __restrict__ lo, int n4)
{
    int i = blockIdx.x * 256 + threadIdx.x;
    if (i >= n4) return;
    float4 v = in[i];
    __half2 h0 = __floats2half2_rn(v.x, v.y);
    __half2 h1 = __floats2half2_rn(v.z, v.w);
    __half2 l0 = __floats2half2_rn(v.x - __half2float(__low2half(h0)),
                                   v.y - __half2float(__high2half(h0)));
    __half2 l1 = __floats2half2_rn(v.z - __half2float(__low2half(h1)),
                                   v.w - __half2float(__high2half(h1)));
    hi[i * 2 + 0] = h0;
    hi[i * 2 + 1] = h1;
    lo[i * 2 + 0] = l0;
    lo[i * 2 + 1] = l1;
}

// W [K,N] fp32 -> W^T [N,K] fp16 (tiled transpose)
__global__ void conv_wT_kernel(const float* __restrict__ W,
                               __half* __restrict__ Th, int Kd, int Nd)
{
    __shared__ float t[32][33];
    const int n0 = blockIdx.x * 32, k0 = blockIdx.y * 32;
    const int tx = threadIdx.x, ty = threadIdx.y;
#pragma unroll
    for (int j = 0; j < 32; j += 8)
        t[ty + j][tx] = W[(size_t)(k0 + ty + j) * Nd + n0 + tx];
    __syncthreads();
#pragma unroll
    for (int j = 0; j < 32; j += 8) {
        float v = t[tx][ty + j];
        Th[(size_t)(n0 + ty + j) * Kd + k0 + tx] = __float2half_rn(v);
    }
}

// ---------------------------------------------------------------------------
// fp16 2-product mma.sync GEMM: 128x128 tile, 8 warps, BK=32, pitch-40 smem,
// 2-stage cp.async pipeline, 2 CTAs/SM.
// NEW: warp tile 32x64 (4m x 2n warp grid), B via ldmatrix.x4 (two n-blocks
// per LDSM) -> 8 LDSM per 32 MMAs (was 12).
// mode 0: fp32 C (+bias). mode 1: QKV epilogue -> Q hi/lo fp16 (pre-scaled),
// K/V single fp16, all in [B,H,S,D].
// ---------------------------------------------------------------------------
#define BK      32
#define PITCH   40                       // fp16 units (80 B rows, conflict-free)
#define TILE_B  (128 * PITCH * 2)        // 10240 B
#define STAGE_B (3 * TILE_B)             // 30720 B (Ah, Al, W)
#define GEMM_SMEM (2 * STAGE_B)          // 61440 B

#define QSCALE  0.1803368801111244f      // 0.125 * log2(e)

static __device__ __forceinline__ void issue_stage(
    uint32_t sstage, const __half* __restrict__ Ahg,
    const __half* __restrict__ Alg, const __half* __restrict__ Bg,
    int bm0, int bn0, int K, int kof, int tid)
{
    const int r = tid >> 1;               // 0..127
    const int c0 = (tid & 1) * 2;         // chunk pair
#pragma unroll
    for (int cc = 0; cc < 2; cc++) {
        const int c = c0 + cc;
        const uint32_t so = (uint32_t)(r * (PITCH * 2) + c * 16);
        const size_t ga = (size_t)(bm0 + r) * K + kof + c * 8;
        const size_t gb = (size_t)(bn0 + r) * K + kof + c * 8;
        cp_async16(sstage + 0 * TILE_B + so, Ahg + ga);
        cp_async16(sstage + 1 * TILE_B + so, Alg + ga);
        cp_async16(sstage + 2 * TILE_B + so, Bg + gb);
    }
}

__global__ __launch_bounds__(256, 2)
void gemm_f16x2_kernel(
    const __half* __restrict__ Ahg, const __half* __restrict__ Alg,
    const __half* __restrict__ Bg,
    const float* __restrict__ bias, float* __restrict__ C,
    int M, int N, int K, int mode,
    __half* __restrict__ kg, __half* __restrict__ qh,
    __half* __restrict__ ql, __half* __restrict__ vg)
{
    extern __shared__ char smem[];
    const uint32_t sbase = smem_u32(smem);
    const int tid  = threadIdx.x;
    const int wid  = tid >> 5;
    const int lane = tid & 31;
    const int bm0 = blockIdx.y * 128;
    const int bn0 = blockIdx.x * 128;

    const int wm = (wid & 3) * 32;       // warp m offset (4 positions)
    const int wn = (wid >> 2) * 64;      // warp n offset (2 positions)

    float acc[2][8][4];
#pragma unroll
    for (int i = 0; i < 2; i++)
#pragma unroll
        for (int j = 0; j < 8; j++)
#pragma unroll
            for (int c = 0; c < 4; c++) acc[i][j][c] = 0.f;

    const int nk = K / BK;   // 32

    issue_stage(sbase + 0 * STAGE_B, Ahg, Alg, Bg, bm0, bn0, K, 0, tid);
    CP_COMMIT();
    issue_stage(sbase + 1 * STAGE_B, Ahg, Alg, Bg, bm0, bn0, K, BK, tid);
    CP_COMMIT();

    // A x4: rows m (lane&15), k-half (lane>>4)
    const uint32_t a_off = (uint32_t)(lane & 15) * (PITCH * 2) + (uint32_t)(lane >> 4) * 16;
    // B x4: rows n { (lane>>4)*8 + (lane&7) }, k-half ((lane>>3)&1)  (R6-validated)
    const uint32_t b_off = ((uint32_t)((lane >> 4) * 8 + (lane & 7))) * (PITCH * 2)
                         + (uint32_t)((lane >> 3) & 1) * 16;

    for (int it = 0; it < nk; it++) {
        CP_WAIT1();
        __syncthreads();
        const uint32_t st = sbase + (it & 1) * STAGE_B;
#pragma unroll
        for (int ks = 0; ks < 2; ks++) {
            uint32_t ah[2][4], al[2][4];
#pragma unroll
            for (int i = 0; i < 2; i++) {
                const uint32_t ro = st + (uint32_t)(wm + i * 16) * (PITCH * 2)
                                  + (uint32_t)(ks * 32) + a_off;
                ldmatrix_x4(ah[i], ro);
                ldmatrix_x4(al[i], ro + TILE_B);
            }
#pragma unroll
            for (int jp = 0; jp < 4; jp++) {
                uint32_t b4[4];
                const uint32_t ro = st + 2 * TILE_B + (uint32_t)(wn + jp * 16) * (PITCH * 2)
                                  + (uint32_t)(ks * 32) + b_off;
                ldmatrix_x4(b4, ro);
                const int j0 = jp * 2, j1 = j0 + 1;
#pragma unroll
                for (int i = 0; i < 2; i++) {
                    mma_f16(acc[i][j0], ah[i], &b4[0]);
                    mma_f16(acc[i][j1], ah[i], &b4[2]);
                }
#pragma unroll
                for (int i = 0; i < 2; i++) {
                    mma_f16(acc[i][j0], al[i], &b4[0]);
                    mma_f16(acc[i][j1], al[i], &b4[2]);
                }
            }
        }
        __syncthreads();
        if (it + 2 < nk)
            issue_stage(st, Ahg, Alg, Bg, bm0, bn0, K, (it + 2) * BK, tid);
        CP_COMMIT();
    }

    const int lr = lane >> 2;
    const int lc = (lane & 3) * 2;
#pragma unroll
    for (int i = 0; i < 2; i++) {
#pragma unroll
        for (int j = 0; j < 8; j++) {
            const int col = bn0 + wn + j * 8 + lc;
            const float bx = bias[col], by = bias[col + 1];
#pragma unroll
            for (int h2 = 0; h2 < 2; h2++) {
                const int row = bm0 + wm + i * 16 + lr + h2 * 8;
                float vx = acc[i][j][h2 * 2 + 0] + bx;
                float vy = acc[i][j][h2 * 2 + 1] + by;
                if (mode == 0) {
                    float2 v = make_float2(vx, vy);
                    *(float2*)&C[(size_t)row * N + col] = v;
                } else {
                    const int sec = col >> 10;
                    const int hh  = (col >> 6) & 15;
                    const int d   = col & 63;
                    const int b_  = row >> 11;
                    const int s   = row & 2047;
                    const size_t off = (((size_t)(b_ * NH + hh)) * S_LEN + s) * HD + d;
                    if (sec == 1) {
                        vx *= QSCALE; vy *= QSCALE;
                        __half2 hv = __floats2half2_rn(vx, vy);
                        __half2 lv = __floats2half2_rn(
                            vx - __half2float(__low2half(hv)),
                            vy - __half2float(__high2half(hv)));
                        *(__half2*)&qh[off] = hv;
                        *(__half2*)&ql[off] = lv;
                    } else {
                        __half2 hv = __floats2half2_rn(vx, vy);
                        *(__half2*)&((sec == 0) ? kg : vg)[off] = hv;
                    }
                }
            }
        }
    }
}

// ---------------------------------------------------------------------------
// Flash attention (causal), fp16 2-product scheme.
// Block: 128 q-rows x (B*H). 8 warps, each warp m16 x n64.
// Q exact fp16 hi/lo; K, V single fp16. K via ldmatrix.x4 (j-pairs),
// V via ldmatrix.x4.trans (jd-pairs) -> half the KV LDSM count.
// 3-stage cp.async pipeline, one sync per tile, 2 CTAs/SM (92 KB smem).
// ---------------------------------------------------------------------------
#define KPITCH 144                       // bytes per 64-dim fp16 row (72 fp16)
#define QT (128 * KPITCH)                // 18432 B per Q component
#define CT (64 * KPITCH)                 // 9216 B per K or V tile
#define KVNST 3
#define ATT_SMEM (2 * QT + KVNST * 2 * CT)   // 92160 B

static __device__ __forceinline__ void issue_kv(
    uint32_t dst, const __half* __restrict__ Kg, const __half* __restrict__ Vg,
    size_t gbase, int k0, int tid)
{
    const int r = tid >> 2;
    const int c = tid & 3;
    const size_t g = gbase + (size_t)(k0 + r) * HD;
#pragma unroll
    for (int cc = 0; cc < 2; cc++) {
        const int ch = c + cc * 4;
        const uint32_t so = (uint32_t)(r * KPITCH + ch * 16);
        cp_async16(dst + 0 * CT + so, Kg + g + ch * 8);
        cp_async16(dst + 1 * CT + so, Vg + g + ch * 8);
    }
}

__global__ __launch_bounds__(256, 2)
void attn_mma_kernel(
    const __half* __restrict__ Qh, const __half* __restrict__ Ql,
    const __half* __restrict__ Kg, const __half* __restrict__ Vg,
    __half* __restrict__ Oh, __half* __restrict__ Ol)
{
    extern __shared__ char smem[];
    const uint32_t sb = smem_u32(smem);
    const uint32_t sQ = sb;                  // Qh tile, Ql at +QT
    const uint32_t sKV = sb + 2 * QT;        // KVNST stages of 2*CT

    const int tid = threadIdx.x;
    const int lane = tid & 31;
    const int w = tid >> 5;
    const int qb = (int)gridDim.x - 1 - (int)blockIdx.x;   // long blocks first
    const int bh = blockIdx.y;
    const int q0 = qb * 128;
    const size_t base = (size_t)bh * S_LEN * HD;

    // load Q hi/lo tile (group 0)
    {
        const int r = tid >> 1;
        const int c0 = (tid & 1) * 4;
#pragma unroll
        for (int c = c0; c < c0 + 4; c++) {
            const uint32_t so = (uint32_t)(r * KPITCH + c * 16);
            const size_t g = base + (size_t)(q0 + r) * HD + c * 8;
            cp_async16(sQ + so, Qh + g);
            cp_async16(sQ + QT + so, Ql + g);
        }
    }
    CP_COMMIT();

    const int nt = 2 * qb + 2;
    issue_kv(sKV + 0 * 2 * CT, Kg, Vg, base, 0, tid);
    CP_COMMIT();
    if (nt > 1) {
        issue_kv(sKV + 1 * 2 * CT, Kg, Vg, base, 64, tid);
    }
    CP_COMMIT();

    CP_WAIT2();          // Q done (kv0, kv1 may be pending)
    __syncthreads();

    // resident Q fragments (fp16 hi/lo)
    const int wm = w * 16;
    uint32_t qfh[4][4], qfl[4][4];
    {
        const uint32_t ab = sQ + (uint32_t)((wm + (lane & 15)) * KPITCH + (lane >> 4) * 16);
#pragma unroll
        for (int kk = 0; kk < 4; kk++) {
            ldmatrix_x4(qfh[kk], ab + kk * 32);
            ldmatrix_x4(qfl[kk], ab + QT + kk * 32);
        }
    }

    float o[8][4];
#pragma unroll
    for (int j = 0; j < 8; j++)
#pragma unroll
        for (int c = 0; c < 4; c++) o[j][c] = 0.f;
    float m0 = -1e30f, m1 = -1e30f, l0 = 0.f, l1 = 0.f;

    // K x4: rows { (lane>>4)*8 + (lane&7) }, k-half ((lane>>3)&1)
    const uint32_t kb4_off = ((uint32_t)((lane >> 4) * 8 + (lane & 7))) * KPITCH
                           + (uint32_t)((lane >> 3) & 1) * 16;
    // V x4 trans: rows (lane&15), col-half (lane>>4)*16
    const uint32_t vb4_off = (uint32_t)(lane & 15) * KPITCH + (uint32_t)(lane >> 4) * 16;

    int stage = 0, wstage = 2 % KVNST;
    for (int it = 0; it < nt; it++) {
        CP_WAIT1();          // kv(it) done (<=1 pending: kv(it+1))
        __syncthreads();     // visible; all warps finished stage (it-1)
        if (it + 2 < nt) {
            issue_kv(sKV + wstage * 2 * CT, Kg, Vg, base, (it + 2) * 64, tid);
            CP_COMMIT();
        } else {
            CP_COMMIT();     // keep group counts uniform
        }

        const int k0 = it * 64;
        const bool active = (k0 <= q0 + wm + 15);
        if (active) {
            const uint32_t st = sKV + stage * 2 * CT;

            // ---- S = Q K^T (fp16x2), K via x4 j-pairs ----
            float s[8][4];
#pragma unroll
            for (int j = 0; j < 8; j++)
#pragma unroll
                for (int c = 0; c < 4; c++) s[j][c] = 0.f;

            const uint32_t kb_ = st + kb4_off;
#pragma unroll
            for (int kk = 0; kk < 4; kk++) {
#pragma unroll
                for (int jp = 0; jp < 4; jp++) {
                    uint32_t k4[4];
                    ldmatrix_x4(k4, kb_ + (uint32_t)(jp * 16 * KPITCH + kk * 32));
                    const int j0 = jp * 2, j1 = j0 + 1;
                    mma_f16(s[j0], qfh[kk], &k4[0]);
                    mma_f16(s[j1], qfh[kk], &k4[2]);
                    mma_f16(s[j0], qfl[kk], &k4[0]);
                    mma_f16(s[j1], qfl[kk], &k4[2]);
                }
            }

            // ---- causal mask (log2 domain; Q pre-scaled) ----
            if (k0 + 63 > q0 + wm) {
#pragma unroll
                for (int j = 0; j < 8; j++)
#pragma unroll
                    for (int c = 0; c < 4; c++) {
                        const int kc = k0 + j * 8 + 2 * (lane & 3) + (c & 1);
                        const int rq = q0 + wm + (lane >> 2) + (c >> 1) * 8;
                        if (kc > rq) s[j][c] = -1e30f;
                    }
            }

            // ---- online softmax (exp2 domain) ----
            float mx0 = -1e30f, mx1 = -1e30f;
#pragma unroll
            for (int j = 0; j < 8; j++) {
                mx0 = fmaxf(mx0, fmaxf(s[j][0], s[j][1]));
                mx1 = fmaxf(mx1, fmaxf(s[j][2], s[j][3]));
            }
            mx0 = fmaxf(mx0, __shfl_xor_sync(0xffffffffu, mx0, 1));
            mx0 = fmaxf(mx0, __shfl_xor_sync(0xffffffffu, mx0, 2));
            mx1 = fmaxf(mx1, __shfl_xor_sync(0xffffffffu, mx1, 1));
            mx1 = fmaxf(mx1, __shfl_xor_sync(0xffffffffu, mx1, 2));

            const float mn0 = fmaxf(m0, mx0);
            const float mn1 = fmaxf(m1, mx1);
            const float f0 = ex2f(m0 - mn0);
            const float f1 = ex2f(m1 - mn1);
            m0 = mn0; m1 = mn1;

            float sum0 = 0.f, sum1 = 0.f;
#pragma unroll
            for (int j = 0; j < 8; j++) {
                s[j][0] = ex2f(s[j][0] - mn0);
                s[j][1] = ex2f(s[j][1] - mn0);
                s[j][2] = ex2f(s[j][2] - mn1);
                s[j][3] = ex2f(s[j][3] - mn1);
                sum0 += s[j][0] + s[j][1];
                sum1 += s[j][2] + s[j][3];
            }
            sum0 += __shfl_xor_sync(0xffffffffu, sum0, 1);
            sum0 += __shfl_xor_sync(0xffffffffu, sum0, 2);
            sum1 += __shfl_xor_sync(0xffffffffu, sum1, 1);
            sum1 += __shfl_xor_sync(0xffffffffu, sum1, 2);
            l0 = l0 * f0 + sum0;
            l1 = l1 * f1 + sum1;

#pragma unroll
            for (int j = 0; j < 8; j++) {
                o[j][0] *= f0; o[j][1] *= f0;
                o[j][2] *= f1; o[j][3] *= f1;
            }

            // ---- O += P V (fp16x2): P exact fp16 hi/lo, V via x4.trans ----
            const uint32_t vb_ = st + CT + vb4_off;
#pragma unroll
            for (int t = 0; t < 4; t++) {
                uint32_t ph[4], pl[4];
#pragma unroll
                for (int half = 0; half < 2; half++) {
                    const float* sp = s[2 * t + half];
                    __half2 h01 = __floats2half2_rn(sp[0], sp[1]);
                    __half2 h23 = __floats2half2_rn(sp[2], sp[3]);
                    __half2 r01 = __floats2half2_rn(
                        sp[0] - __half2float(__low2half(h01)),
                        sp[1] - __half2float(__high2half(h01)));
                    __half2 r23 = __floats2half2_rn(
                        sp[2] - __half2float(__low2half(h23)),
                        sp[3] - __half2float(__high2half(h23)));
                    ph[2 * half + 0] = *(uint32_t*)&h01;
                    ph[2 * half + 1] = *(uint32_t*)&h23;
                    pl[2 * half + 0] = *(uint32_t*)&r01;
                    pl[2 * half + 1] = *(uint32_t*)&r23;
                }
#pragma unroll
                for (int jq = 0; jq < 4; jq++) {
                    uint32_t v4[4];
                    ldmatrix_x4_trans(v4, vb_ + (uint32_t)(16 * t * KPITCH + jq * 32));
                    const int jd0 = jq * 2, jd1 = jd0 + 1;
                    mma_f16(o[jd0], ph, &v4[0]);
                    mma_f16(o[jd1], ph, &v4[2]);
                    mma_f16(o[jd0], pl, &v4[0]);
                    mma_f16(o[jd1], pl, &v4[2]);
                }
            }
        }

        if (++stage == KVNST) stage = 0;
        if (++wstage == KVNST) wstage = 0;
    }

    // ---- epilogue: normalize, split fp16 hi/lo, write [M,E] ----
    const int b = bh >> 4;
    const int h = bh & 15;
    const float inv0 = 1.0f / l0;
    const float inv1 = 1.0f / l1;
    const int r0 = b * S_LEN + q0 + wm + (lane >> 2);
    const int colb = h * HD + 2 * (lane & 3);
#pragma unroll
    for (int jd = 0; jd < 8; jd++) {
        const int col = colb + jd * 8;
#pragma unroll
        for (int h2 = 0; h2 < 2; h2++) {
            const float inv = h2 ? inv1 : inv0;
            const float vx = o[jd][h2 * 2 + 0] * inv;
            const float vy = o[jd][h2 * 2 + 1] * inv;
            const size_t off = (size_t)(r0 + h2 * 8) * EMB + col;
            __half2 hv = __floats2half2_rn(vx, vy);
            __half2 lv = __floats2half2_rn(vx - __half2float(__low2half(hv)),
                                           vy - __half2float(__high2half(hv)));
            *(__half2*)&Oh[off] = hv;
            *(__half2*)&Ol[off] = lv;
        }
    }
}

// ---------------------------------------------------------------------------
// Launch
// ---------------------------------------------------------------------------
extern "C" void kernel_launch(void* const* d_in, const int* in_sizes, int n_in,
                              void* d_out, int out_size)
{
    const float* x      = (const float*)d_in[0];
    const float* W_qkv  = (const float*)d_in[1];
    const float* b_qkv  = (const float*)d_in[2];
    const float* W_proj = (const float*)d_in[3];
    const float* b_proj = (const float*)d_in[4];
    float* out = (float*)d_out;

    __half *Ah, *Al, *WQ, *WP, *Qh, *Ql, *Kg, *Vg;
    cudaGetSymbolAddress((void**)&Ah, g_Ah);
    cudaGetSymbolAddress((void**)&Al, g_Al);
    cudaGetSymbolAddress((void**)&WQ, g_WQ);
    cudaGetSymbolAddress((void**)&WP, g_WP);
    cudaGetSymbolAddress((void**)&Qh, g_Qh);
    cudaGetSymbolAddress((void**)&Ql, g_Ql);
    cudaGetSymbolAddress((void**)&Kg, g_K);
    cudaGetSymbolAddress((void**)&Vg, g_V);

    cudaFuncSetAttribute(gemm_f16x2_kernel,
                         cudaFuncAttributeMaxDynamicSharedMemorySize, GEMM_SMEM);
    cudaFuncSetAttribute(attn_mma_kernel,
                         cudaFuncAttributeMaxDynamicSharedMemorySize, ATT_SMEM);

    // 0) pre-convert weights (transposed, fp16) and input activations (fp16 hi/lo)
    {
        dim3 blk(32, 8);
        conv_wT_kernel<<<dim3(3 * EMB / 32, EMB / 32), blk>>>(W_qkv, WQ, EMB, 3 * EMB);
        conv_wT_kernel<<<dim3(EMB / 32, EMB / 32), blk>>>(W_proj, WP, EMB, EMB);
        const int n4 = MTOT * EMB / 4;
        conv_act_kernel<<<n4 / 256, 256>>>((const float4*)x, (__half2*)Ah, (__half2*)Al, n4);
    }

    // 1) QKV projection (fp16x2) -> Q hi/lo fp16 (pre-scaled), K/V single fp16
    gemm_f16x2_kernel<<<dim3(3 * EMB / 128, MTOT / 128), 256, GEMM_SMEM>>>(
        Ah, Al, WQ, b_qkv, nullptr, MTOT, 3 * EMB, EMB, 1,
        Kg, Qh, Ql, Vg);

    // 2) fused causal flash attention (fp16x2) -> fp16 hi/lo Ah/Al
    attn_mma_kernel<<<dim3(S_LEN / 128, BATCH * NH), 256, ATT_SMEM>>>(
        Qh, Ql, Kg, Vg, Ah, Al);

    // 3) output projection (fp16x2) -> fp32 out
    gemm_f16x2_kernel<<<dim3(EMB / 128, MTOT / 128), 256, GEMM_SMEM>>>(
        Ah, Al, WP, b_proj, out, MTOT, EMB, EMB, 0,
        nullptr, nullptr, nullptr, nullptr);
}

// round 12
// speedup vs baseline: 2.0074x; 1.2963x over previous
#include <cuda_runtime.h>
#include <cuda_bf16.h>
#include <cuda_fp16.h>
#include <cstdint>

#define BATCH 4
#define S_LEN 2048
#define EMB   1024
#define NH    16
#define HD    64
#define MTOT  (BATCH * S_LEN)   // 8192

// ---------------------------------------------------------------------------
// Device-global scratch (allocation-free requirement)
// ---------------------------------------------------------------------------
static __device__ __half g_A [MTOT * EMB];               // GEMM A (single fp16)
static __device__ __half g_WQ[3 * EMB * EMB];            // W_qkv^T fp16 [N=3072,K=1024]
static __device__ __half g_WP[EMB * EMB];                // W_proj^T fp16 [N=1024,K=1024]

static __device__ __half g_Qh[BATCH * NH * S_LEN * HD];  // Q hi (pre-scaled, fp16)
static __device__ __half g_Ql[BATCH * NH * S_LEN * HD];  // Q lo
static __device__ __half g_K [BATCH * NH * S_LEN * HD];  // K single fp16
static __device__ __half g_V [BATCH * NH * S_LEN * HD];  // V single fp16

// ---------------------------------------------------------------------------
// Portable PTX helpers (compute_100-safe)
// ---------------------------------------------------------------------------
static __device__ __forceinline__ uint32_t smem_u32(const void* p) {
    uint32_t a;
    asm("{ .reg .u64 t; cvta.to.shared.u64 t, %1; cvt.u32.u64 %0, t; }" : "=r"(a) : "l"(p));
    return a;
}
static __device__ __forceinline__ void cp_async16(uint32_t dst, const void* src) {
    asm volatile("cp.async.cg.shared.global [%0], [%1], 16;" :: "r"(dst), "l"(src) : "memory");
}
#define CP_COMMIT() asm volatile("cp.async.commit_group;" ::: "memory")
#define CP_WAIT1()  asm volatile("cp.async.wait_group 1;" ::: "memory")
#define CP_WAIT2()  asm volatile("cp.async.wait_group 2;" ::: "memory")

static __device__ __forceinline__ void ldmatrix_x4(uint32_t* r, uint32_t addr) {
    asm volatile("ldmatrix.sync.aligned.m8n8.x4.shared.b16 {%0,%1,%2,%3}, [%4];"
                 : "=r"(r[0]), "=r"(r[1]), "=r"(r[2]), "=r"(r[3]) : "r"(addr));
}
static __device__ __forceinline__ void ldmatrix_x4_trans(uint32_t* r, uint32_t addr) {
    asm volatile("ldmatrix.sync.aligned.m8n8.x4.trans.shared.b16 {%0,%1,%2,%3}, [%4];"
                 : "=r"(r[0]), "=r"(r[1]), "=r"(r[2]), "=r"(r[3]) : "r"(addr));
}
static __device__ __forceinline__ void mma_f16(float* d, const uint32_t* a, const uint32_t* b) {
    asm volatile("mma.sync.aligned.m16n8k16.row.col.f32.f16.f16.f32 "
                 "{%0,%1,%2,%3}, {%4,%5,%6,%7}, {%8,%9}, {%0,%1,%2,%3};"
                 : "+f"(d[0]), "+f"(d[1]), "+f"(d[2]), "+f"(d[3])
                 : "r"(a[0]), "r"(a[1]), "r"(a[2]), "r"(a[3]), "r"(b[0]), "r"(b[1]));
}
static __device__ __forceinline__ float ex2f(float x) {
    float y;
    asm("ex2.approx.ftz.f32 %0, %1;" : "=f"(y) : "f"(x));
    return y;
}

// ---------------------------------------------------------------------------
// Pre-processing kernels
// ---------------------------------------------------------------------------
__global__ void conv_act_kernel(const float4* __restrict__ in,
                                __half2* __restrict__ o16, int n4)
{
    int i = blockIdx.x * 256 + threadIdx.x;
    if (i >= n4) return;
    float4 v = in[i];
    o16[i * 2 + 0] = __floats2half2_rn(v.x, v.y);
    o16[i * 2 + 1] = __floats2half2_rn(v.z, v.w);
}

// W [K,N] fp32 -> W^T [N,K] fp16 (tiled transpose)
__global__ void conv_wT_kernel(const float* __restrict__ W,
                               __half* __restrict__ Th, int Kd, int Nd)
{
    __shared__ float t[32][33];
    const int n0 = blockIdx.x * 32, k0 = blockIdx.y * 32;
    const int tx = threadIdx.x, ty = threadIdx.y;
#pragma unroll
    for (int j = 0; j < 32; j += 8)
        t[ty + j][tx] = W[(size_t)(k0 + ty + j) * Nd + n0 + tx];
    __syncthreads();
#pragma unroll
    for (int j = 0; j < 32; j += 8) {
        float v = t[tx][ty + j];
        Th[(size_t)(n0 + ty + j) * Kd + k0 + tx] = __float2half_rn(v);
    }
}

// ---------------------------------------------------------------------------
// Single-fp16 mma.sync GEMM: 128x128 tile, 8 warps (32x64 each, 4m x 2n),
// BK=64 (4 k16 steps -> long MMA bursts), pitch-72 fp16 rows (144 B),
// 2-stage cp.async pipeline, 2 CTAs/SM (72 KB smem).
// mode 0: fp32 C (+bias). mode 1: QKV epilogue -> Q hi/lo fp16 (pre-scaled),
// K/V single fp16, all in [B,H,S,D].
// ---------------------------------------------------------------------------
#define BK      64
#define GP      144                      // bytes per 64-fp16 row (72 fp16)
#define TILE_B  (128 * GP)               // 18432 B
#define STAGE_B (2 * TILE_B)             // 36864 B (A, W)
#define GEMM_SMEM (2 * STAGE_B)          // 73728 B

#define QSCALE  0.1803368801111244f      // 0.125 * log2(e)

static __device__ __forceinline__ void issue_stage(
    uint32_t sstage, const __half* __restrict__ Ag, const __half* __restrict__ Bg,
    int bm0, int bn0, int K, int kof, int tid)
{
    const int r  = tid >> 1;              // 0..127
    const int c0 = (tid & 1) * 4;         // 4 chunks of 16B each
    const size_t ga = (size_t)(bm0 + r) * K + kof;
    const size_t gb = (size_t)(bn0 + r) * K + kof;
    const uint32_t so = (uint32_t)(r * GP);
#pragma unroll
    for (int cc = 0; cc < 4; cc++) {
        const int c = c0 + cc;
        cp_async16(sstage + 0 * TILE_B + so + c * 16, Ag + ga + c * 8);
        cp_async16(sstage + 1 * TILE_B + so + c * 16, Bg + gb + c * 8);
    }
}

__global__ __launch_bounds__(256, 2)
void gemm_f16_kernel(
    const __half* __restrict__ Ag, const __half* __restrict__ Bg,
    const float* __restrict__ bias, float* __restrict__ C,
    int M, int N, int K, int mode,
    __half* __restrict__ kg, __half* __restrict__ qh,
    __half* __restrict__ ql, __half* __restrict__ vg)
{
    extern __shared__ char smem[];
    const uint32_t sbase = smem_u32(smem);
    const int tid  = threadIdx.x;
    const int wid  = tid >> 5;
    const int lane = tid & 31;
    const int bm0 = blockIdx.y * 128;
    const int bn0 = blockIdx.x * 128;

    const int wm = (wid & 3) * 32;       // warp m offset (4 positions)
    const int wn = (wid >> 2) * 64;      // warp n offset (2 positions)

    float acc[2][8][4];
#pragma unroll
    for (int i = 0; i < 2; i++)
#pragma unroll
        for (int j = 0; j < 8; j++)
#pragma unroll
            for (int c = 0; c < 4; c++) acc[i][j][c] = 0.f;

    const int nk = K / BK;   // 16

    issue_stage(sbase + 0 * STAGE_B, Ag, Bg, bm0, bn0, K, 0, tid);
    CP_COMMIT();
    issue_stage(sbase + 1 * STAGE_B, Ag, Bg, bm0, bn0, K, BK, tid);
    CP_COMMIT();

    // A x4: rows m (lane&15), k-half (lane>>4)
    const uint32_t a_off = (uint32_t)(lane & 15) * GP + (uint32_t)(lane >> 4) * 16;
    // B x4: rows n { (lane>>4)*8 + (lane&7) }, k-half ((lane>>3)&1)
    const uint32_t b_off = ((uint32_t)((lane >> 4) * 8 + (lane & 7))) * GP
                         + (uint32_t)((lane >> 3) & 1) * 16;

    for (int it = 0; it < nk; it++) {
        CP_WAIT1();
        __syncthreads();
        const uint32_t st = sbase + (it & 1) * STAGE_B;
#pragma unroll
        for (int ks = 0; ks < 4; ks++) {
            uint32_t a4[2][4];
#pragma unroll
            for (int i = 0; i < 2; i++) {
                const uint32_t ro = st + (uint32_t)(wm + i * 16) * GP
                                  + (uint32_t)(ks * 32) + a_off;
                ldmatrix_x4(a4[i], ro);
            }
#pragma unroll
            for (int jp = 0; jp < 4; jp++) {
                uint32_t b4[4];
                const uint32_t ro = st + TILE_B + (uint32_t)(wn + jp * 16) * GP
                                  + (uint32_t)(ks * 32) + b_off;
                ldmatrix_x4(b4, ro);
                const int j0 = jp * 2, j1 = j0 + 1;
#pragma unroll
                for (int i = 0; i < 2; i++) {
                    mma_f16(acc[i][j0], a4[i], &b4[0]);
                    mma_f16(acc[i][j1], a4[i], &b4[2]);
                }
            }
        }
        __syncthreads();
        if (it + 2 < nk)
            issue_stage(st, Ag, Bg, bm0, bn0, K, (it + 2) * BK, tid);
        CP_COMMIT();
    }

    const int lr = lane >> 2;
    const int lc = (lane & 3) * 2;
#pragma unroll
    for (int i = 0; i < 2; i++) {
#pragma unroll
        for (int j = 0; j < 8; j++) {
            const int col = bn0 + wn + j * 8 + lc;
            const float bx = bias[col], by = bias[col + 1];
#pragma unroll
            for (int h2 = 0; h2 < 2; h2++) {
                const int row = bm0 + wm + i * 16 + lr + h2 * 8;
                float vx = acc[i][j][h2 * 2 + 0] + bx;
                float vy = acc[i][j][h2 * 2 + 1] + by;
                if (mode == 0) {
                    float2 v = make_float2(vx, vy);
                    *(float2*)&C[(size_t)row * N + col] = v;
                } else {
                    const int sec = col >> 10;
                    const int hh  = (col >> 6) & 15;
                    const int d   = col & 63;
                    const int b_  = row >> 11;
                    const int s   = row & 2047;
                    const size_t off = (((size_t)(b_ * NH + hh)) * S_LEN + s) * HD + d;
                    if (sec == 1) {
                        vx *= QSCALE; vy *= QSCALE;
                        __half2 hv = __floats2half2_rn(vx, vy);
                        __half2 lv = __floats2half2_rn(
                            vx - __half2float(__low2half(hv)),
                            vy - __half2float(__high2half(hv)));
                        *(__half2*)&qh[off] = hv;
                        *(__half2*)&ql[off] = lv;
                    } else {
                        __half2 hv = __floats2half2_rn(vx, vy);
                        *(__half2*)&((sec == 0) ? kg : vg)[off] = hv;
                    }
                }
            }
        }
    }
}

// ---------------------------------------------------------------------------
// Flash attention (causal), fp16 2-product scheme (unchanged from R11).
// Block: 128 q-rows x (B*H). 8 warps, each warp m16 x n64.
// Q exact fp16 hi/lo; K, V single fp16. K via ldmatrix.x4 (j-pairs),
// V via ldmatrix.x4.trans (jd-pairs).
// 3-stage cp.async pipeline, one sync per tile, 2 CTAs/SM (92 KB smem).
// Output written as SINGLE fp16 into the proj GEMM input buffer.
// ---------------------------------------------------------------------------
#define KPITCH 144                       // bytes per 64-dim fp16 row (72 fp16)
#define QT (128 * KPITCH)                // 18432 B per Q component
#define CT (64 * KPITCH)                 // 9216 B per K or V tile
#define KVNST 3
#define ATT_SMEM (2 * QT + KVNST * 2 * CT)   // 92160 B

static __device__ __forceinline__ void issue_kv(
    uint32_t dst, const __half* __restrict__ Kg, const __half* __restrict__ Vg,
    size_t gbase, int k0, int tid)
{
    const int r = tid >> 2;
    const int c = tid & 3;
    const size_t g = gbase + (size_t)(k0 + r) * HD;
#pragma unroll
    for (int cc = 0; cc < 2; cc++) {
        const int ch = c + cc * 4;
        const uint32_t so = (uint32_t)(r * KPITCH + ch * 16);
        cp_async16(dst + 0 * CT + so, Kg + g + ch * 8);
        cp_async16(dst + 1 * CT + so, Vg + g + ch * 8);
    }
}

__global__ __launch_bounds__(256, 2)
void attn_mma_kernel(
    const __half* __restrict__ Qh, const __half* __restrict__ Ql,
    const __half* __restrict__ Kg, const __half* __restrict__ Vg,
    __half* __restrict__ Og)
{
    extern __shared__ char smem[];
    const uint32_t sb = smem_u32(smem);
    const uint32_t sQ = sb;                  // Qh tile, Ql at +QT
    const uint32_t sKV = sb + 2 * QT;        // KVNST stages of 2*CT

    const int tid = threadIdx.x;
    const int lane = tid & 31;
    const int w = tid >> 5;
    const int qb = (int)gridDim.x - 1 - (int)blockIdx.x;   // long blocks first
    const int bh = blockIdx.y;
    const int q0 = qb * 128;
    const size_t base = (size_t)bh * S_LEN * HD;

    // load Q hi/lo tile (group 0)
    {
        const int r = tid >> 1;
        const int c0 = (tid & 1) * 4;
#pragma unroll
        for (int c = c0; c < c0 + 4; c++) {
            const uint32_t so = (uint32_t)(r * KPITCH + c * 16);
            const size_t g = base + (size_t)(q0 + r) * HD + c * 8;
            cp_async16(sQ + so, Qh + g);
            cp_async16(sQ + QT + so, Ql + g);
        }
    }
    CP_COMMIT();

    const int nt = 2 * qb + 2;
    issue_kv(sKV + 0 * 2 * CT, Kg, Vg, base, 0, tid);
    CP_COMMIT();
    if (nt > 1) {
        issue_kv(sKV + 1 * 2 * CT, Kg, Vg, base, 64, tid);
    }
    CP_COMMIT();

    CP_WAIT2();          // Q done (kv0, kv1 may be pending)
    __syncthreads();

    // resident Q fragments (fp16 hi/lo)
    const int wm = w * 16;
    uint32_t qfh[4][4], qfl[4][4];
    {
        const uint32_t ab = sQ + (uint32_t)((wm + (lane & 15)) * KPITCH + (lane >> 4) * 16);
#pragma unroll
        for (int kk = 0; kk < 4; kk++) {
            ldmatrix_x4(qfh[kk], ab + kk * 32);
            ldmatrix_x4(qfl[kk], ab + QT + kk * 32);
        }
    }

    float o[8][4];
#pragma unroll
    for (int j = 0; j < 8; j++)
#pragma unroll
        for (int c = 0; c < 4; c++) o[j][c] = 0.f;
    float m0 = -1e30f, m1 = -1e30f, l0 = 0.f, l1 = 0.f;

    const uint32_t kb4_off = ((uint32_t)((lane >> 4) * 8 + (lane & 7))) * KPITCH
                           + (uint32_t)((lane >> 3) & 1) * 16;
    const uint32_t vb4_off = (uint32_t)(lane & 15) * KPITCH + (uint32_t)(lane >> 4) * 16;

    int stage = 0, wstage = 2 % KVNST;
    for (int it = 0; it < nt; it++) {
        CP_WAIT1();          // kv(it) done (<=1 pending: kv(it+1))
        __syncthreads();     // visible; all warps finished stage (it-1)
        if (it + 2 < nt) {
            issue_kv(sKV + wstage * 2 * CT, Kg, Vg, base, (it + 2) * 64, tid);
            CP_COMMIT();
        } else {
            CP_COMMIT();     // keep group counts uniform
        }

        const int k0 = it * 64;
        const bool active = (k0 <= q0 + wm + 15);
        if (active) {
            const uint32_t st = sKV + stage * 2 * CT;

            // ---- S = Q K^T (fp16x2), K via x4 j-pairs ----
            float s[8][4];
#pragma unroll
            for (int j = 0; j < 8; j++)
#pragma unroll
                for (int c = 0; c < 4; c++) s[j][c] = 0.f;

            const uint32_t kb_ = st + kb4_off;
#pragma unroll
            for (int kk = 0; kk < 4; kk++) {
#pragma unroll
                for (int jp = 0; jp < 4; jp++) {
                    uint32_t k4[4];
                    ldmatrix_x4(k4, kb_ + (uint32_t)(jp * 16 * KPITCH + kk * 32));
                    const int j0 = jp * 2, j1 = j0 + 1;
                    mma_f16(s[j0], qfh[kk], &k4[0]);
                    mma_f16(s[j1], qfh[kk], &k4[2]);
                    mma_f16(s[j0], qfl[kk], &k4[0]);
                    mma_f16(s[j1], qfl[kk], &k4[2]);
                }
            }

            // ---- causal mask (log2 domain; Q pre-scaled) ----
            if (k0 + 63 > q0 + wm) {
#pragma unroll
                for (int j = 0; j < 8; j++)
#pragma unroll
                    for (int c = 0; c < 4; c++) {
                        const int kc = k0 + j * 8 + 2 * (lane & 3) + (c & 1);
                        const int rq = q0 + wm + (lane >> 2) + (c >> 1) * 8;
                        if (kc > rq) s[j][c] = -1e30f;
                    }
            }

            // ---- online softmax (exp2 domain) ----
            float mx0 = -1e30f, mx1 = -1e30f;
#pragma unroll
            for (int j = 0; j < 8; j++) {
                mx0 = fmaxf(mx0, fmaxf(s[j][0], s[j][1]));
                mx1 = fmaxf(mx1, fmaxf(s[j][2], s[j][3]));
            }
            mx0 = fmaxf(mx0, __shfl_xor_sync(0xffffffffu, mx0, 1));
            mx0 = fmaxf(mx0, __shfl_xor_sync(0xffffffffu, mx0, 2));
            mx1 = fmaxf(mx1, __shfl_xor_sync(0xffffffffu, mx1, 1));
            mx1 = fmaxf(mx1, __shfl_xor_sync(0xffffffffu, mx1, 2));

            const float mn0 = fmaxf(m0, mx0);
            const float mn1 = fmaxf(m1, mx1);
            const float f0 = ex2f(m0 - mn0);
            const float f1 = ex2f(m1 - mn1);
            m0 = mn0; m1 = mn1;

            float sum0 = 0.f, sum1 = 0.f;
#pragma unroll
            for (int j = 0; j < 8; j++) {
                s[j][0] = ex2f(s[j][0] - mn0);
                s[j][1] = ex2f(s[j][1] - mn0);
                s[j][2] = ex2f(s[j][2] - mn1);
                s[j][3] = ex2f(s[j][3] - mn1);
                sum0 += s[j][0] + s[j][1];
                sum1 += s[j][2] + s[j][3];
            }
            sum0 += __shfl_xor_sync(0xffffffffu, sum0, 1);
            sum0 += __shfl_xor_sync(0xffffffffu, sum0, 2);
            sum1 += __shfl_xor_sync(0xffffffffu, sum1, 1);
            sum1 += __shfl_xor_sync(0xffffffffu, sum1, 2);
            l0 = l0 * f0 + sum0;
            l1 = l1 * f1 + sum1;

#pragma unroll
            for (int j = 0; j < 8; j++) {
                o[j][0] *= f0; o[j][1] *= f0;
                o[j][2] *= f1; o[j][3] *= f1;
            }

            // ---- O += P V (fp16x2): P exact fp16 hi/lo, V via x4.trans ----
            const uint32_t vb_ = st + CT + vb4_off;
#pragma unroll
            for (int t = 0; t < 4; t++) {
                uint32_t ph[4], pl[4];
#pragma unroll
                for (int half = 0; half < 2; half++) {
                    const float* sp = s[2 * t + half];
                    __half2 h01 = __floats2half2_rn(sp[0], sp[1]);
                    __half2 h23 = __floats2half2_rn(sp[2], sp[3]);
                    __half2 r01 = __floats2half2_rn(
                        sp[0] - __half2float(__low2half(h01)),
                        sp[1] - __half2float(__high2half(h01)));
                    __half2 r23 = __floats2half2_rn(
                        sp[2] - __half2float(__low2half(h23)),
                        sp[3] - __half2float(__high2half(h23)));
                    ph[2 * half + 0] = *(uint32_t*)&h01;
                    ph[2 * half + 1] = *(uint32_t*)&h23;
                    pl[2 * half + 0] = *(uint32_t*)&r01;
                    pl[2 * half + 1] = *(uint32_t*)&r23;
                }
#pragma unroll
                for (int jq = 0; jq < 4; jq++) {
                    uint32_t v4[4];
                    ldmatrix_x4_trans(v4, vb_ + (uint32_t)(16 * t * KPITCH + jq * 32));
                    const int jd0 = jq * 2, jd1 = jd0 + 1;
                    mma_f16(o[jd0], ph, &v4[0]);
                    mma_f16(o[jd1], ph, &v4[2]);
                    mma_f16(o[jd0], pl, &v4[0]);
                    mma_f16(o[jd1], pl, &v4[2]);
                }
            }
        }

        if (++stage == KVNST) stage = 0;
        if (++wstage == KVNST) wstage = 0;
    }

    // ---- epilogue: normalize, write single fp16 [M,E] ----
    const int b = bh >> 4;
    const int h = bh & 15;
    const float inv0 = 1.0f / l0;
    const float inv1 = 1.0f / l1;
    const int r0 = b * S_LEN + q0 + wm + (lane >> 2);
    const int colb = h * HD + 2 * (lane & 3);
#pragma unroll
    for (int jd = 0; jd < 8; jd++) {
        const int col = colb + jd * 8;
#pragma unroll
        for (int h2 = 0; h2 < 2; h2++) {
            const float inv = h2 ? inv1 : inv0;
            const float vx = o[jd][h2 * 2 + 0] * inv;
            const float vy = o[jd][h2 * 2 + 1] * inv;
            const size_t off = (size_t)(r0 + h2 * 8) * EMB + col;
            *(__half2*)&Og[off] = __floats2half2_rn(vx, vy);
        }
    }
}

// ---------------------------------------------------------------------------
// Launch
// ---------------------------------------------------------------------------
extern "C" void kernel_launch(void* const* d_in, const int* in_sizes, int n_in,
                              void* d_out, int out_size)
{
    const float* x      = (const float*)d_in[0];
    const float* W_qkv  = (const float*)d_in[1];
    const float* b_qkv  = (const float*)d_in[2];
    const float* W_proj = (const float*)d_in[3];
    const float* b_proj = (const float*)d_in[4];
    float* out = (float*)d_out;

    __half *Ag, *WQ, *WP, *Qh, *Ql, *Kg, *Vg;
    cudaGetSymbolAddress((void**)&Ag, g_A);
    cudaGetSymbolAddress((void**)&WQ, g_WQ);
    cudaGetSymbolAddress((void**)&WP, g_WP);
    cudaGetSymbolAddress((void**)&Qh, g_Qh);
    cudaGetSymbolAddress((void**)&Ql, g_Ql);
    cudaGetSymbolAddress((void**)&Kg, g_K);
    cudaGetSymbolAddress((void**)&Vg, g_V);

    cudaFuncSetAttribute(gemm_f16_kernel,
                         cudaFuncAttributeMaxDynamicSharedMemorySize, GEMM_SMEM);
    cudaFuncSetAttribute(attn_mma_kernel,
                         cudaFuncAttributeMaxDynamicSharedMemorySize, ATT_SMEM);

    // 0) pre-convert weights (transposed, fp16) and input activations (fp16)
    {
        dim3 blk(32, 8);
        conv_wT_kernel<<<dim3(3 * EMB / 32, EMB / 32), blk>>>(W_qkv, WQ, EMB, 3 * EMB);
        conv_wT_kernel<<<dim3(EMB / 32, EMB / 32), blk>>>(W_proj, WP, EMB, EMB);
        const int n4 = MTOT * EMB / 4;
        conv_act_kernel<<<n4 / 256, 256>>>((const float4*)x, (__half2*)Ag, n4);
    }

    // 1) QKV projection (single fp16) -> Q hi/lo fp16 (pre-scaled), K/V single fp16
    gemm_f16_kernel<<<dim3(3 * EMB / 128, MTOT / 128), 256, GEMM_SMEM>>>(
        Ag, WQ, b_qkv, nullptr, MTOT, 3 * EMB, EMB, 1,
        Kg, Qh, Ql, Vg);

    // 2) fused causal flash attention (fp16x2) -> single fp16 Ag
    attn_mma_kernel<<<dim3(S_LEN / 128, BATCH * NH), 256, ATT_SMEM>>>(
        Qh, Ql, Kg, Vg, Ag);

    // 3) output projection (single fp16) -> fp32 out
    gemm_f16_kernel<<<dim3(EMB / 128, MTOT / 128), 256, GEMM_SMEM>>>(
        Ag, WP, b_proj, out, MTOT, EMB, EMB, 0,
        nullptr, nullptr, nullptr, nullptr);
}

// round 13
// speedup vs baseline: 2.3833x; 1.1873x over previous
#include <cuda_runtime.h>
#include <cuda_bf16.h>
#include <cuda_fp16.h>
#include <cstdint>

#define BATCH 4
#define S_LEN 2048
#define EMB   1024
#define NH    16
#define HD    64
#define MTOT  (BATCH * S_LEN)   // 8192

// ---------------------------------------------------------------------------
// Device-global scratch (allocation-free requirement)
// ---------------------------------------------------------------------------
static __device__ __half g_A [MTOT * EMB];               // GEMM A (single fp16)
static __device__ __half g_WQ[3 * EMB * EMB];            // W_qkv^T fp16 [N=3072,K=1024]
static __device__ __half g_WP[EMB * EMB];                // W_proj^T fp16 [N=1024,K=1024]

static __device__ __half g_Q [BATCH * NH * S_LEN * HD];  // Q single fp16 (pre-scaled)
static __device__ __half g_K [BATCH * NH * S_LEN * HD];  // K single fp16
static __device__ __half g_V [BATCH * NH * S_LEN * HD];  // V single fp16

// ---------------------------------------------------------------------------
// Portable PTX helpers (compute_100-safe)
// ---------------------------------------------------------------------------
static __device__ __forceinline__ uint32_t smem_u32(const void* p) {
    uint32_t a;
    asm("{ .reg .u64 t; cvta.to.shared.u64 t, %1; cvt.u32.u64 %0, t; }" : "=r"(a) : "l"(p));
    return a;
}
static __device__ __forceinline__ void cp_async16(uint32_t dst, const void* src) {
    asm volatile("cp.async.cg.shared.global [%0], [%1], 16;" :: "r"(dst), "l"(src) : "memory");
}
#define CP_COMMIT() asm volatile("cp.async.commit_group;" ::: "memory")
#define CP_WAIT1()  asm volatile("cp.async.wait_group 1;" ::: "memory")
#define CP_WAIT2()  asm volatile("cp.async.wait_group 2;" ::: "memory")

static __device__ __forceinline__ void ldmatrix_x4(uint32_t* r, uint32_t addr) {
    asm volatile("ldmatrix.sync.aligned.m8n8.x4.shared.b16 {%0,%1,%2,%3}, [%4];"
                 : "=r"(r[0]), "=r"(r[1]), "=r"(r[2]), "=r"(r[3]) : "r"(addr));
}
static __device__ __forceinline__ void ldmatrix_x4_trans(uint32_t* r, uint32_t addr) {
    asm volatile("ldmatrix.sync.aligned.m8n8.x4.trans.shared.b16 {%0,%1,%2,%3}, [%4];"
                 : "=r"(r[0]), "=r"(r[1]), "=r"(r[2]), "=r"(r[3]) : "r"(addr));
}
static __device__ __forceinline__ void mma_f16(float* d, const uint32_t* a, const uint32_t* b) {
    asm volatile("mma.sync.aligned.m16n8k16.row.col.f32.f16.f16.f32 "
                 "{%0,%1,%2,%3}, {%4,%5,%6,%7}, {%8,%9}, {%0,%1,%2,%3};"
                 : "+f"(d[0]), "+f"(d[1]), "+f"(d[2]), "+f"(d[3])
                 : "r"(a[0]), "r"(a[1]), "r"(a[2]), "r"(a[3]), "r"(b[0]), "r"(b[1]));
}
static __device__ __forceinline__ float ex2f(float x) {
    float y;
    asm("ex2.approx.ftz.f32 %0, %1;" : "=f"(y) : "f"(x));
    return y;
}

// ---------------------------------------------------------------------------
// Pre-processing kernels
// ---------------------------------------------------------------------------
__global__ void conv_act_kernel(const float4* __restrict__ in,
                                __half2* __restrict__ o16, int n4)
{
    int i = blockIdx.x * 256 + threadIdx.x;
    if (i >= n4) return;
    float4 v = in[i];
    o16[i * 2 + 0] = __floats2half2_rn(v.x, v.y);
    o16[i * 2 + 1] = __floats2half2_rn(v.z, v.w);
}

// W [K,N] fp32 -> W^T [N,K] fp16 (tiled transpose)
__global__ void conv_wT_kernel(const float* __restrict__ W,
                               __half* __restrict__ Th, int Kd, int Nd)
{
    __shared__ float t[32][33];
    const int n0 = blockIdx.x * 32, k0 = blockIdx.y * 32;
    const int tx = threadIdx.x, ty = threadIdx.y;
#pragma unroll
    for (int j = 0; j < 32; j += 8)
        t[ty + j][tx] = W[(size_t)(k0 + ty + j) * Nd + n0 + tx];
    __syncthreads();
#pragma unroll
    for (int j = 0; j < 32; j += 8) {
        float v = t[tx][ty + j];
        Th[(size_t)(n0 + ty + j) * Kd + k0 + tx] = __float2half_rn(v);
    }
}

// ---------------------------------------------------------------------------
// Single-fp16 mma.sync GEMM (R12, unchanged): 128x128 tile, 8 warps (32x64),
// BK=64, pitch-72 fp16 rows (144 B), 2-stage cp.async pipeline, 2 CTAs/SM.
// mode 0: fp32 C (+bias). mode 1: QKV epilogue -> Q (pre-scaled), K, V
// all single fp16 in [B,H,S,D].
// ---------------------------------------------------------------------------
#define BK      64
#define GP      144                      // bytes per 64-fp16 row (72 fp16)
#define TILE_B  (128 * GP)               // 18432 B
#define STAGE_B (2 * TILE_B)             // 36864 B (A, W)
#define GEMM_SMEM (2 * STAGE_B)          // 73728 B

#define QSCALE  0.1803368801111244f      // 0.125 * log2(e)

static __device__ __forceinline__ void issue_stage(
    uint32_t sstage, const __half* __restrict__ Ag, const __half* __restrict__ Bg,
    int bm0, int bn0, int K, int kof, int tid)
{
    const int r  = tid >> 1;              // 0..127
    const int c0 = (tid & 1) * 4;         // 4 chunks of 16B each
    const size_t ga = (size_t)(bm0 + r) * K + kof;
    const size_t gb = (size_t)(bn0 + r) * K + kof;
    const uint32_t so = (uint32_t)(r * GP);
#pragma unroll
    for (int cc = 0; cc < 4; cc++) {
        const int c = c0 + cc;
        cp_async16(sstage + 0 * TILE_B + so + c * 16, Ag + ga + c * 8);
        cp_async16(sstage + 1 * TILE_B + so + c * 16, Bg + gb + c * 8);
    }
}

__global__ __launch_bounds__(256, 2)
void gemm_f16_kernel(
    const __half* __restrict__ Ag, const __half* __restrict__ Bg,
    const float* __restrict__ bias, float* __restrict__ C,
    int M, int N, int K, int mode,
    __half* __restrict__ kg, __half* __restrict__ qg, __half* __restrict__ vg)
{
    extern __shared__ char smem[];
    const uint32_t sbase = smem_u32(smem);
    const int tid  = threadIdx.x;
    const int wid  = tid >> 5;
    const int lane = tid & 31;
    const int bm0 = blockIdx.y * 128;
    const int bn0 = blockIdx.x * 128;

    const int wm = (wid & 3) * 32;       // warp m offset (4 positions)
    const int wn = (wid >> 2) * 64;      // warp n offset (2 positions)

    float acc[2][8][4];
#pragma unroll
    for (int i = 0; i < 2; i++)
#pragma unroll
        for (int j = 0; j < 8; j++)
#pragma unroll
            for (int c = 0; c < 4; c++) acc[i][j][c] = 0.f;

    const int nk = K / BK;   // 16

    issue_stage(sbase + 0 * STAGE_B, Ag, Bg, bm0, bn0, K, 0, tid);
    CP_COMMIT();
    issue_stage(sbase + 1 * STAGE_B, Ag, Bg, bm0, bn0, K, BK, tid);
    CP_COMMIT();

    const uint32_t a_off = (uint32_t)(lane & 15) * GP + (uint32_t)(lane >> 4) * 16;
    const uint32_t b_off = ((uint32_t)((lane >> 4) * 8 + (lane & 7))) * GP
                         + (uint32_t)((lane >> 3) & 1) * 16;

    for (int it = 0; it < nk; it++) {
        CP_WAIT1();
        __syncthreads();
        const uint32_t st = sbase + (it & 1) * STAGE_B;
#pragma unroll
        for (int ks = 0; ks < 4; ks++) {
            uint32_t a4[2][4];
#pragma unroll
            for (int i = 0; i < 2; i++) {
                const uint32_t ro = st + (uint32_t)(wm + i * 16) * GP
                                  + (uint32_t)(ks * 32) + a_off;
                ldmatrix_x4(a4[i], ro);
            }
#pragma unroll
            for (int jp = 0; jp < 4; jp++) {
                uint32_t b4[4];
                const uint32_t ro = st + TILE_B + (uint32_t)(wn + jp * 16) * GP
                                  + (uint32_t)(ks * 32) + b_off;
                ldmatrix_x4(b4, ro);
                const int j0 = jp * 2, j1 = j0 + 1;
#pragma unroll
                for (int i = 0; i < 2; i++) {
                    mma_f16(acc[i][j0], a4[i], &b4[0]);
                    mma_f16(acc[i][j1], a4[i], &b4[2]);
                }
            }
        }
        __syncthreads();
        if (it + 2 < nk)
            issue_stage(st, Ag, Bg, bm0, bn0, K, (it + 2) * BK, tid);
        CP_COMMIT();
    }

    const int lr = lane >> 2;
    const int lc = (lane & 3) * 2;
#pragma unroll
    for (int i = 0; i < 2; i++) {
#pragma unroll
        for (int j = 0; j < 8; j++) {
            const int col = bn0 + wn + j * 8 + lc;
            const float bx = bias[col], by = bias[col + 1];
#pragma unroll
            for (int h2 = 0; h2 < 2; h2++) {
                const int row = bm0 + wm + i * 16 + lr + h2 * 8;
                float vx = acc[i][j][h2 * 2 + 0] + bx;
                float vy = acc[i][j][h2 * 2 + 1] + by;
                if (mode == 0) {
                    float2 v = make_float2(vx, vy);
                    *(float2*)&C[(size_t)row * N + col] = v;
                } else {
                    const int sec = col >> 10;
                    const int hh  = (col >> 6) & 15;
                    const int d   = col & 63;
                    const int b_  = row >> 11;
                    const int s   = row & 2047;
                    const size_t off = (((size_t)(b_ * NH + hh)) * S_LEN + s) * HD + d;
                    if (sec == 1) { vx *= QSCALE; vy *= QSCALE; }
                    __half* dst = (sec == 0) ? kg : ((sec == 1) ? qg : vg);
                    *(__half2*)&dst[off] = __floats2half2_rn(vx, vy);
                }
            }
        }
    }
}

// ---------------------------------------------------------------------------
// Flash attention (causal), single-fp16 operands everywhere.
// Block: 128 q-rows x (B*H). 8 warps, each warp m16 x n64.
// Q, K, V, P all single fp16. K via ldmatrix.x4 (j-pairs),
// V via ldmatrix.x4.trans (jd-pairs).
// 3-stage cp.async pipeline, one sync per tile, 2 CTAs/SM (74 KB smem).
// Output written as single fp16 into the proj GEMM input buffer.
// ---------------------------------------------------------------------------
#define KPITCH 144                       // bytes per 64-dim fp16 row (72 fp16)
#define QT (128 * KPITCH)                // 18432 B (Q tile, single)
#define CT (64 * KPITCH)                 // 9216 B per K or V tile
#define KVNST 3
#define ATT_SMEM (QT + KVNST * 2 * CT)   // 73728 B

static __device__ __forceinline__ void issue_kv(
    uint32_t dst, const __half* __restrict__ Kg, const __half* __restrict__ Vg,
    size_t gbase, int k0, int tid)
{
    const int r = tid >> 2;
    const int c = tid & 3;
    const size_t g = gbase + (size_t)(k0 + r) * HD;
#pragma unroll
    for (int cc = 0; cc < 2; cc++) {
        const int ch = c + cc * 4;
        const uint32_t so = (uint32_t)(r * KPITCH + ch * 16);
        cp_async16(dst + 0 * CT + so, Kg + g + ch * 8);
        cp_async16(dst + 1 * CT + so, Vg + g + ch * 8);
    }
}

__global__ __launch_bounds__(256, 2)
void attn_mma_kernel(
    const __half* __restrict__ Qg,
    const __half* __restrict__ Kg, const __half* __restrict__ Vg,
    __half* __restrict__ Og)
{
    extern __shared__ char smem[];
    const uint32_t sb = smem_u32(smem);
    const uint32_t sQ = sb;                  // Q tile (single)
    const uint32_t sKV = sb + QT;            // KVNST stages of 2*CT

    const int tid = threadIdx.x;
    const int lane = tid & 31;
    const int w = tid >> 5;
    const int qb = (int)gridDim.x - 1 - (int)blockIdx.x;   // long blocks first
    const int bh = blockIdx.y;
    const int q0 = qb * 128;
    const size_t base = (size_t)bh * S_LEN * HD;

    // load Q tile (group 0)
    {
        const int r = tid >> 1;
        const int c0 = (tid & 1) * 4;
#pragma unroll
        for (int c = c0; c < c0 + 4; c++) {
            const uint32_t so = (uint32_t)(r * KPITCH + c * 16);
            cp_async16(sQ + so, Qg + base + (size_t)(q0 + r) * HD + c * 8);
        }
    }
    CP_COMMIT();

    const int nt = 2 * qb + 2;
    issue_kv(sKV + 0 * 2 * CT, Kg, Vg, base, 0, tid);
    CP_COMMIT();
    if (nt > 1) {
        issue_kv(sKV + 1 * 2 * CT, Kg, Vg, base, 64, tid);
    }
    CP_COMMIT();

    CP_WAIT2();          // Q done (kv0, kv1 may be pending)
    __syncthreads();

    // resident Q fragments (single fp16)
    const int wm = w * 16;
    uint32_t qf[4][4];
    {
        const uint32_t ab = sQ + (uint32_t)((wm + (lane & 15)) * KPITCH + (lane >> 4) * 16);
#pragma unroll
        for (int kk = 0; kk < 4; kk++)
            ldmatrix_x4(qf[kk], ab + kk * 32);
    }

    float o[8][4];
#pragma unroll
    for (int j = 0; j < 8; j++)
#pragma unroll
        for (int c = 0; c < 4; c++) o[j][c] = 0.f;
    float m0 = -1e30f, m1 = -1e30f, l0 = 0.f, l1 = 0.f;

    const uint32_t kb4_off = ((uint32_t)((lane >> 4) * 8 + (lane & 7))) * KPITCH
                           + (uint32_t)((lane >> 3) & 1) * 16;
    const uint32_t vb4_off = (uint32_t)(lane & 15) * KPITCH + (uint32_t)(lane >> 4) * 16;

    int stage = 0, wstage = 2 % KVNST;
    for (int it = 0; it < nt; it++) {
        CP_WAIT1();          // kv(it) done (<=1 pending: kv(it+1))
        __syncthreads();     // visible; all warps finished stage (it-1)
        if (it + 2 < nt) {
            issue_kv(sKV + wstage * 2 * CT, Kg, Vg, base, (it + 2) * 64, tid);
            CP_COMMIT();
        } else {
            CP_COMMIT();     // keep group counts uniform
        }

        const int k0 = it * 64;
        const bool active = (k0 <= q0 + wm + 15);
        if (active) {
            const uint32_t st = sKV + stage * 2 * CT;

            // ---- S = Q K^T (single fp16), K via x4 j-pairs ----
            float s[8][4];
#pragma unroll
            for (int j = 0; j < 8; j++)
#pragma unroll
                for (int c = 0; c < 4; c++) s[j][c] = 0.f;

            const uint32_t kb_ = st + kb4_off;
#pragma unroll
            for (int kk = 0; kk < 4; kk++) {
#pragma unroll
                for (int jp = 0; jp < 4; jp++) {
                    uint32_t k4[4];
                    ldmatrix_x4(k4, kb_ + (uint32_t)(jp * 16 * KPITCH + kk * 32));
                    const int j0 = jp * 2, j1 = j0 + 1;
                    mma_f16(s[j0], qf[kk], &k4[0]);
                    mma_f16(s[j1], qf[kk], &k4[2]);
                }
            }

            // ---- causal mask (log2 domain; Q pre-scaled) ----
            if (k0 + 63 > q0 + wm) {
#pragma unroll
                for (int j = 0; j < 8; j++)
#pragma unroll
                    for (int c = 0; c < 4; c++) {
                        const int kc = k0 + j * 8 + 2 * (lane & 3) + (c & 1);
                        const int rq = q0 + wm + (lane >> 2) + (c >> 1) * 8;
                        if (kc > rq) s[j][c] = -1e30f;
                    }
            }

            // ---- online softmax (exp2 domain) ----
            float mx0 = -1e30f, mx1 = -1e30f;
#pragma unroll
            for (int j = 0; j < 8; j++) {
                mx0 = fmaxf(mx0, fmaxf(s[j][0], s[j][1]));
                mx1 = fmaxf(mx1, fmaxf(s[j][2], s[j][3]));
            }
            mx0 = fmaxf(mx0, __shfl_xor_sync(0xffffffffu, mx0, 1));
            mx0 = fmaxf(mx0, __shfl_xor_sync(0xffffffffu, mx0, 2));
            mx1 = fmaxf(mx1, __shfl_xor_sync(0xffffffffu, mx1, 1));
            mx1 = fmaxf(mx1, __shfl_xor_sync(0xffffffffu, mx1, 2));

            const float mn0 = fmaxf(m0, mx0);
            const float mn1 = fmaxf(m1, mx1);
            const float f0 = ex2f(m0 - mn0);
            const float f1 = ex2f(m1 - mn1);
            m0 = mn0; m1 = mn1;

            float sum0 = 0.f, sum1 = 0.f;
#pragma unroll
            for (int j = 0; j < 8; j++) {
                s[j][0] = ex2f(s[j][0] - mn0);
                s[j][1] = ex2f(s[j][1] - mn0);
                s[j][2] = ex2f(s[j][2] - mn1);
                s[j][3] = ex2f(s[j][3] - mn1);
                sum0 += s[j][0] + s[j][1];
                sum1 += s[j][2] + s[j][3];
            }
            sum0 += __shfl_xor_sync(0xffffffffu, sum0, 1);
            sum0 += __shfl_xor_sync(0xffffffffu, sum0, 2);
            sum1 += __shfl_xor_sync(0xffffffffu, sum1, 1);
            sum1 += __shfl_xor_sync(0xffffffffu, sum1, 2);
            l0 = l0 * f0 + sum0;
            l1 = l1 * f1 + sum1;

#pragma unroll
            for (int j = 0; j < 8; j++) {
                o[j][0] *= f0; o[j][1] *= f0;
                o[j][2] *= f1; o[j][3] *= f1;
            }

            // ---- O += P V (single fp16 P), V via x4.trans ----
            const uint32_t vb_ = st + CT + vb4_off;
#pragma unroll
            for (int t = 0; t < 4; t++) {
                uint32_t ph[4];
#pragma unroll
                for (int half = 0; half < 2; half++) {
                    const float* sp = s[2 * t + half];
                    __half2 h01 = __floats2half2_rn(sp[0], sp[1]);
                    __half2 h23 = __floats2half2_rn(sp[2], sp[3]);
                    ph[2 * half + 0] = *(uint32_t*)&h01;
                    ph[2 * half + 1] = *(uint32_t*)&h23;
                }
#pragma unroll
                for (int jq = 0; jq < 4; jq++) {
                    uint32_t v4[4];
                    ldmatrix_x4_trans(v4, vb_ + (uint32_t)(16 * t * KPITCH + jq * 32));
                    const int jd0 = jq * 2, jd1 = jd0 + 1;
                    mma_f16(o[jd0], ph, &v4[0]);
                    mma_f16(o[jd1], ph, &v4[2]);
                }
            }
        }

        if (++stage == KVNST) stage = 0;
        if (++wstage == KVNST) wstage = 0;
    }

    // ---- epilogue: normalize, write single fp16 [M,E] ----
    const int b = bh >> 4;
    const int h = bh & 15;
    const float inv0 = 1.0f / l0;
    const float inv1 = 1.0f / l1;
    const int r0 = b * S_LEN + q0 + wm + (lane >> 2);
    const int colb = h * HD + 2 * (lane & 3);
#pragma unroll
    for (int jd = 0; jd < 8; jd++) {
        const int col = colb + jd * 8;
#pragma unroll
        for (int h2 = 0; h2 < 2; h2++) {
            const float inv = h2 ? inv1 : inv0;
            const float vx = o[jd][h2 * 2 + 0] * inv;
            const float vy = o[jd][h2 * 2 + 1] * inv;
            const size_t off = (size_t)(r0 + h2 * 8) * EMB + col;
            *(__half2*)&Og[off] = __floats2half2_rn(vx, vy);
        }
    }
}

// ---------------------------------------------------------------------------
// Launch
// ---------------------------------------------------------------------------
extern "C" void kernel_launch(void* const* d_in, const int* in_sizes, int n_in,
                              void* d_out, int out_size)
{
    const float* x      = (const float*)d_in[0];
    const float* W_qkv  = (const float*)d_in[1];
    const float* b_qkv  = (const float*)d_in[2];
    const float* W_proj = (const float*)d_in[3];
    const float* b_proj = (const float*)d_in[4];
    float* out = (float*)d_out;

    __half *Ag, *WQ, *WP, *Qg, *Kg, *Vg;
    cudaGetSymbolAddress((void**)&Ag, g_A);
    cudaGetSymbolAddress((void**)&WQ, g_WQ);
    cudaGetSymbolAddress((void**)&WP, g_WP);
    cudaGetSymbolAddress((void**)&Qg, g_Q);
    cudaGetSymbolAddress((void**)&Kg, g_K);
    cudaGetSymbolAddress((void**)&Vg, g_V);

    cudaFuncSetAttribute(gemm_f16_kernel,
                         cudaFuncAttributeMaxDynamicSharedMemorySize, GEMM_SMEM);
    cudaFuncSetAttribute(attn_mma_kernel,
                         cudaFuncAttributeMaxDynamicSharedMemorySize, ATT_SMEM);

    // 0) pre-convert weights (transposed, fp16) and input activations (fp16)
    {
        dim3 blk(32, 8);
        conv_wT_kernel<<<dim3(3 * EMB / 32, EMB / 32), blk>>>(W_qkv, WQ, EMB, 3 * EMB);
        conv_wT_kernel<<<dim3(EMB / 32, EMB / 32), blk>>>(W_proj, WP, EMB, EMB);
        const int n4 = MTOT * EMB / 4;
        conv_act_kernel<<<n4 / 256, 256>>>((const float4*)x, (__half2*)Ag, n4);
    }

    // 1) QKV projection (single fp16) -> Q (pre-scaled), K, V single fp16
    gemm_f16_kernel<<<dim3(3 * EMB / 128, MTOT / 128), 256, GEMM_SMEM>>>(
        Ag, WQ, b_qkv, nullptr, MTOT, 3 * EMB, EMB, 1, Kg, Qg, Vg);

    // 2) fused causal flash attention (single fp16) -> fp16 Ag
    attn_mma_kernel<<<dim3(S_LEN / 128, BATCH * NH), 256, ATT_SMEM>>>(
        Qg, Kg, Vg, Ag);

    // 3) output projection (single fp16) -> fp32 out
    gemm_f16_kernel<<<dim3(EMB / 128, MTOT / 128), 256, GEMM_SMEM>>>(
        Ag, WP, b_proj, out, MTOT, EMB, EMB, 0, nullptr, nullptr, nullptr);
}